// round 14
// baseline (speedup 1.0000x reference)
#include <cuda_runtime.h>
#include <cuda_fp16.h>
#include <math.h>
#include <stdint.h>

#define NB 16
#define NS 4096
#define NDIN 64
#define NE 512
#define NM 128
#define NL 4
#define ROWS (NB*NS)        /* 65536 */
#define HID (4*NE)          /* 2048 */
#define KV_SPLIT 8

// ---------------- scratch (device globals; no allocations allowed) ----------
__device__ float g_h [(size_t)ROWS*NE];
__device__ float g_k [(size_t)ROWS*NE];
__device__ float g_pk[(size_t)ROWS*NM];   // pk logits (fp32)
__device__ float g_kv32[(size_t)NB*NM*NE];
__device__ float g_z [NB*NM];
__device__ float g_part [ROWS];   // per-row max (pk pass)
__device__ float g_rowq [ROWS];   // per-row max for pq
__device__ float g_nq  [ROWS];    // per-row sum-of-squares (q)
__device__ float g_nk  [ROWS];    // per-row sum-of-squares (k)
__device__ float g_inv [ROWS];    // per-row 1/den factor
__device__ unsigned g_mxo [1];    // global max (pk), ordered-uint encoding
__device__ unsigned g_mxqo[1];    // global max (pq), ordered-uint encoding
__device__ float g_bmk [NB];      // per-batch max (pk)
__device__ float g_r1[16*256];

// fp16 mirrors
__device__ __half g_h16 [(size_t)ROWS*NE];
__device__ __half g_q16 [(size_t)ROWS*NE];
__device__ __half g_k16 [(size_t)ROWS*NE];
__device__ __half g_v16 [(size_t)ROWS*NE];
__device__ __half g_pq16[(size_t)ROWS*NM];
__device__ __half g_pk16[(size_t)ROWS*NM];
__device__ __half g_kv16[(size_t)NB*NM*NE];
__device__ __half g_ff16[(size_t)ROWS*HID];
__device__ __half g_x16 [(size_t)ROWS*NDIN];
__device__ __half g_wi16[NDIN*NE];
__device__ __half g_wq16[(size_t)NL*NE*NE];
__device__ __half g_wk16[(size_t)NL*NE*NE];
__device__ __half g_wv16[(size_t)NL*NE*NE];
__device__ __half g_wo16[(size_t)NL*NE*NE];
__device__ __half g_r16 [(size_t)NL*NE*NM];
__device__ __half g_w116[(size_t)NL*NE*HID];
__device__ __half g_w216[(size_t)NL*HID*NE];

// ================= helpers =================
__device__ __forceinline__ uint32_t smem_u32(const void* p) {
    uint32_t r;
    asm("{ .reg .u64 t; cvta.to.shared.u64 t, %1; cvt.u32.u64 %0, t; }" : "=r"(r) : "l"(p));
    return r;
}
__device__ __forceinline__ void cp_async16(uint32_t saddr, const void* g) {
    asm volatile("cp.async.cg.shared.global [%0], [%1], 16;" :: "r"(saddr), "l"(g));
}
__device__ __forceinline__ void ldsm_x4(uint32_t r[4], uint32_t addr) {
    asm volatile("ldmatrix.sync.aligned.m8n8.x4.shared.b16 {%0,%1,%2,%3}, [%4];"
                 : "=r"(r[0]), "=r"(r[1]), "=r"(r[2]), "=r"(r[3]) : "r"(addr));
}
__device__ __forceinline__ void ldsm_x4_t(uint32_t r[4], uint32_t addr) {
    asm volatile("ldmatrix.sync.aligned.m8n8.x4.trans.shared.b16 {%0,%1,%2,%3}, [%4];"
                 : "=r"(r[0]), "=r"(r[1]), "=r"(r[2]), "=r"(r[3]) : "r"(addr));
}
__device__ __forceinline__ void mma_f16(float c[4], const uint32_t a[4], const uint32_t b[2]) {
    asm volatile(
        "mma.sync.aligned.m16n8k16.row.col.f32.f16.f16.f32 "
        "{%0,%1,%2,%3}, {%4,%5,%6,%7}, {%8,%9}, {%0,%1,%2,%3};"
        : "+f"(c[0]), "+f"(c[1]), "+f"(c[2]), "+f"(c[3])
        : "r"(a[0]), "r"(a[1]), "r"(a[2]), "r"(a[3]), "r"(b[0]), "r"(b[1]));
}
// monotonic float<->uint encoding: a<=b (float) <=> ford(a)<=ford(b) (uint)
__device__ __forceinline__ unsigned ford(float f) {
    unsigned u = __float_as_uint(f);
    return (u & 0x80000000u) ? ~u : (u | 0x80000000u);
}
__device__ __forceinline__ float funord(unsigned u) {
    return __uint_as_float((u & 0x80000000u) ? (u & 0x7fffffffu) : ~u);
}

// ================= fp16 mma GEMM with fused epilogues =================
// 128 threads / 4 warps; CTA tile 128x128; warp tile 64x64; BK=32, 5 stages.
// MODE 0: plain; MODE 1: SUMSQ; MODE 2: PHI; MODE 3: SCALEROW; MODE 4: RESID;
// MODE 5: PHIEXP; MODE 6: SPLITK (blockIdx.y = k-chunk, atomicAdd fp32 into C).

#define BKH 32
#define A_HS 40
#define T_HS 136
#define HG_STAGES 5

template<int TRANS_A>
__device__ __forceinline__ void h_fill(const __half* __restrict__ A, int lda,
                                       const __half* __restrict__ B, int ldb,
                                       int m0, int n0, int kof,
                                       uint32_t sa, uint32_t sb, int tid) {
    if (!TRANS_A) {
#pragma unroll
        for (int i = 0; i < 4; i++) {
            int lin = (i << 7) + tid;
            int row = lin >> 2, c = lin & 3;
            cp_async16(sa + (uint32_t)(row * A_HS + (c << 3)) * 2,
                       A + (size_t)(m0 + row) * lda + kof + (c << 3));
        }
    } else {
#pragma unroll
        for (int i = 0; i < 4; i++) {
            int lin = (i << 7) + tid;
            int row = lin >> 4, c = lin & 15;
            cp_async16(sa + (uint32_t)(row * T_HS + (c << 3)) * 2,
                       A + (size_t)(kof + row) * lda + m0 + (c << 3));
        }
    }
#pragma unroll
    for (int i = 0; i < 4; i++) {
        int lin = (i << 7) + tid;
        int row = lin >> 4, c = lin & 15;
        cp_async16(sb + (uint32_t)(row * T_HS + (c << 3)) * 2,
                   B + (size_t)(kof + row) * ldb + n0 + (c << 3));
    }
}

template<int TRANS_A, int ACT, int WF32, int WF16, int MODE>
__global__ __launch_bounds__(128, 2)
void hgemm_k(const __half* __restrict__ A, int lda, size_t sAs,
             const __half* __restrict__ B, int ldb, size_t sBs,
             float* __restrict__ C, __half* __restrict__ C16, int ldc, size_t sCs,
             const float* __restrict__ bias, int K,
             float* __restrict__ aux1, float* __restrict__ aux2)
{
    constexpr int ATILE_B = TRANS_A ? (BKH * T_HS * 2) : (128 * A_HS * 2);
    constexpr int STAGE_B = ATILE_B + BKH * T_HS * 2;

    extern __shared__ __half hsm[];
    uint32_t smb = smem_u32(hsm);
    int tid = threadIdx.x;
    int wid = tid >> 5, lane = tid & 31;
    int group = lane >> 3, lr = lane & 7;
    int g = lane >> 2, t4 = lane & 3;

    A += (size_t)blockIdx.z * sAs;
    B += (size_t)blockIdx.z * sBs;
    int m0 = (MODE == 6) ? 0 : (blockIdx.y << 7);
    int kb = (MODE == 6) ? (blockIdx.y * K) : 0;   // k-chunk base for split-K
    int n0 = blockIdx.x << 7;
    int wm = wid & 1, wn = wid >> 1;

    float c[4][8][4];
#pragma unroll
    for (int a = 0; a < 4; a++)
#pragma unroll
        for (int b = 0; b < 8; b++)
#pragma unroll
            for (int r = 0; r < 4; r++) c[a][b][r] = 0.f;

    int nk = K >> 5;

#pragma unroll
    for (int s = 0; s < HG_STAGES - 1; s++) {
        if (s < nk) {
            uint32_t sa = smb + (uint32_t)s * STAGE_B;
            h_fill<TRANS_A>(A, lda, B, ldb, m0, n0, kb + (s << 5), sa, sa + ATILE_B, tid);
        }
        asm volatile("cp.async.commit_group;");
    }

    int cs = 0;                       // compute stage index
    int fs = HG_STAGES - 1;           // fill stage index
    for (int kt = 0; kt < nk; kt++) {
        asm volatile("cp.async.wait_group %0;" :: "n"(HG_STAGES - 2));
        __syncthreads();

        int nxt = kt + HG_STAGES - 1;
        if (nxt < nk) {
            uint32_t sa = smb + (uint32_t)fs * STAGE_B;
            h_fill<TRANS_A>(A, lda, B, ldb, m0, n0, kb + (nxt << 5), sa, sa + ATILE_B, tid);
        }
        asm volatile("cp.async.commit_group;");
        if (++fs == HG_STAGES) fs = 0;

        uint32_t sa = smb + (uint32_t)cs * STAGE_B;
        uint32_t sb = sa + ATILE_B;
        if (++cs == HG_STAGES) cs = 0;
#pragma unroll
        for (int ks = 0; ks < 2; ks++) {
            uint32_t af[4][4];
#pragma unroll
            for (int mi = 0; mi < 4; mi++) {
                uint32_t addr;
                if (!TRANS_A) {
                    int arow = (wm << 6) + (mi << 4) + ((group & 1) << 3) + lr;
                    int acol = (ks << 4) + ((group >> 1) << 3);
                    addr = sa + (uint32_t)(arow * A_HS + acol) * 2;
                    ldsm_x4(af[mi], addr);
                } else {
                    int krow = (ks << 4) + ((group >> 1) << 3) + lr;
                    int mcol = (wm << 6) + (mi << 4) + ((group & 1) << 3);
                    addr = sa + (uint32_t)(krow * T_HS + mcol) * 2;
                    ldsm_x4_t(af[mi], addr);
                }
            }
            uint32_t bf[4][4];
#pragma unroll
            for (int np = 0; np < 4; np++) {
                int krow = (ks << 4) + ((group & 1) << 3) + lr;
                int ncol = (wn << 6) + (np << 4) + ((group >> 1) << 3);
                ldsm_x4_t(bf[np], sb + (uint32_t)(krow * T_HS + ncol) * 2);
            }
#pragma unroll
            for (int mi = 0; mi < 4; mi++)
#pragma unroll
                for (int ni = 0; ni < 8; ni++)
                    mma_f16(c[mi][ni], af[mi], &bf[ni >> 1][(ni & 1) << 1]);
        }
    }

    // ---- epilogue ----
    if (MODE == 2 || MODE == 5) __syncthreads();     // smem reused as logit stage
    float* stage = (float*)hsm;
    int auxrows = (int)(sCs / (size_t)ldc);
    const float GK = 0.7071067811865476f;
    const float PSCALE = 0.21022410381342865f;   // 512^-0.25
    const float PS2    = 0.02209708691207961f;   // 0.5 * 512^-0.5
#pragma unroll
    for (int mi = 0; mi < 4; mi++) {
        int r = (wm << 6) + (mi << 4) + g;
        size_t rowoff0 = (size_t)blockIdx.z * sCs + (size_t)(m0 + r) * ldc;
        size_t rowoff1 = rowoff0 + (size_t)8 * ldc;
        int ar0 = blockIdx.z * auxrows + m0 + r;
        int ar1 = ar0 + 8;
        float n2a = 0.f, n2b = 0.f, iv0 = 0.f, iv1 = 0.f;
        if (MODE == 2 || MODE == 5) { n2a = aux1[ar0]; n2b = aux1[ar1]; }
        if (MODE == 3) { iv0 = aux1[ar0]; iv1 = aux1[ar1]; }
        float ssq0 = 0.f, ssq1 = 0.f;
#pragma unroll
        for (int ni = 0; ni < 8; ni++) {
            int nn = n0 + (wn << 6) + (ni << 3) + (t4 << 1);
            float v0 = c[mi][ni][0], v1 = c[mi][ni][1];
            float v2 = c[mi][ni][2], v3 = c[mi][ni][3];
            if (bias) {
                float b0 = __ldg(bias + nn), b1 = __ldg(bias + nn + 1);
                v0 += b0; v1 += b1; v2 += b0; v3 += b1;
            }
            if (ACT == 1) {
                v0 = 0.5f * v0 * (1.f + erff(v0 * GK));
                v1 = 0.5f * v1 * (1.f + erff(v1 * GK));
                v2 = 0.5f * v2 * (1.f + erff(v2 * GK));
                v3 = 0.5f * v3 * (1.f + erff(v3 * GK));
            }
            if (MODE == 1) {
                ssq0 += v0 * v0 + v1 * v1;
                ssq1 += v2 * v2 + v3 * v3;
            }
            if (MODE == 2 || MODE == 5) {
                int rl = (wm << 6) + (mi << 4) + g;
                v0 = fmaf(v0, PSCALE, -PS2 * n2a);
                v1 = fmaf(v1, PSCALE, -PS2 * n2a);
                v2 = fmaf(v2, PSCALE, -PS2 * n2b);
                v3 = fmaf(v3, PSCALE, -PS2 * n2b);
                int nl = (wn << 6) + (ni << 3) + (t4 << 1);
                stage[rl * 132 + nl] = v0;       stage[rl * 132 + nl + 1] = v1;
                stage[(rl + 8) * 132 + nl] = v2; stage[(rl + 8) * 132 + nl + 1] = v3;
            }
            if (MODE == 3) { v0 *= iv0; v1 *= iv0; v2 *= iv1; v3 *= iv1; }
            if (MODE == 4) {
                float2 r0 = *(float2*)(C + rowoff0 + nn);
                float2 r1 = *(float2*)(C + rowoff1 + nn);
                v0 += r0.x; v1 += r0.y; v2 += r1.x; v3 += r1.y;
            }
            if (MODE == 6) {
                atomicAdd(C + rowoff0 + nn, v0);
                atomicAdd(C + rowoff0 + nn + 1, v1);
                atomicAdd(C + rowoff1 + nn, v2);
                atomicAdd(C + rowoff1 + nn + 1, v3);
            }
            if (WF32) {
                *(float2*)(C + rowoff0 + nn) = make_float2(v0, v1);
                *(float2*)(C + rowoff1 + nn) = make_float2(v2, v3);
            }
            if (WF16) {
                *(__half2*)(C16 + rowoff0 + nn) = __floats2half2_rn(v0, v1);
                *(__half2*)(C16 + rowoff1 + nn) = __floats2half2_rn(v2, v3);
            }
        }
        if (MODE == 1) {
            ssq0 += __shfl_xor_sync(0xffffffffu, ssq0, 1);
            ssq0 += __shfl_xor_sync(0xffffffffu, ssq0, 2);
            ssq1 += __shfl_xor_sync(0xffffffffu, ssq1, 1);
            ssq1 += __shfl_xor_sync(0xffffffffu, ssq1, 2);
            if (t4 == 0) {
                atomicAdd(&aux1[ar0], ssq0);
                atomicAdd(&aux1[ar1], ssq1);
            }
        }
    }
    if (MODE == 2 || MODE == 5) {
        __syncthreads();
        int rr = tid;                        // one thread per row (128)
        const float* rp = stage + rr * 132;
        float m = -INFINITY;
#pragma unroll
        for (int j = 0; j < 128; j++) m = fmaxf(m, rp[j]);
        aux2[m0 + rr] = m;
        if (MODE == 5) {
            __half* dst = C16 + (size_t)(m0 + rr) * ldc;
#pragma unroll
            for (int j = 0; j < 128; j += 2) {
                float e0 = expf(rp[j]     - m) * 0.08838834764831845f;
                float e1 = expf(rp[j + 1] - m) * 0.08838834764831845f;
                *(__half2*)(dst + j) = __floats2half2_rn(e0, e1);
            }
        }
    }
}

// ================= fp32 fallback SGEMM (head only) =================
#define BM 128
#define BN 128
#define BK 8

template<int ACT>
__global__ __launch_bounds__(256)
void gemm_k(const float* __restrict__ A, int lda,
            const float* __restrict__ Bm, int ldb,
            float* __restrict__ C, int ldc,
            const float* __restrict__ bias,
            int M, int N, int K)
{
    int m0 = blockIdx.y * BM;
    int n0 = blockIdx.x * BN;

    __shared__ float As[BK][BM];
    __shared__ float Bs[BK][BN];

    int tid = threadIdx.x;
    int tx = tid & 15, ty = tid >> 4;

    float acc[8][8];
#pragma unroll
    for (int i = 0; i < 8; i++)
#pragma unroll
        for (int j = 0; j < 8; j++) acc[i][j] = 0.f;

    float ar[8], br[8];

    for (int k0 = 0; k0 < K; k0 += BK) {
        {
            int m  = tid >> 1;
            int kk = (tid & 1) * 4;
            bool mok = (m0 + m) < M;
            const float* src = A + (size_t)(m0 + m) * lda + k0 + kk;
#pragma unroll
            for (int i = 0; i < 4; i++)
                As[kk + i][m] = mok ? src[i] : 0.f;
        }
        {
            int k = tid >> 5;
            int n = (tid & 31) * 4;
            const float* src = Bm + (size_t)(k0 + k) * ldb + n0 + n;
#pragma unroll
            for (int i = 0; i < 4; i++) {
                float vv = 0.f;
                if (n0 + n + i < N) vv = src[i];
                Bs[k][n + i] = vv;
            }
        }
        __syncthreads();
#pragma unroll
        for (int k = 0; k < BK; k++) {
            *(float4*)&ar[0] = *(float4*)&As[k][ty * 4];
            *(float4*)&ar[4] = *(float4*)&As[k][64 + ty * 4];
            *(float4*)&br[0] = *(float4*)&Bs[k][tx * 4];
            *(float4*)&br[4] = *(float4*)&Bs[k][64 + tx * 4];
#pragma unroll
            for (int i = 0; i < 8; i++)
#pragma unroll
                for (int j = 0; j < 8; j++)
                    acc[i][j] = fmaf(ar[i], br[j], acc[i][j]);
        }
        __syncthreads();
    }

#pragma unroll
    for (int i = 0; i < 8; i++) {
        int m = m0 + ((i < 4) ? (ty * 4 + i) : (64 + ty * 4 + i - 4));
        if (m >= M) continue;
#pragma unroll
        for (int j = 0; j < 8; j++) {
            int n = n0 + ((j < 4) ? (tx * 4 + j) : (64 + tx * 4 + j - 4));
            if (n >= N) continue;
            float vv = acc[i][j];
            if (bias) vv += bias[n];
            if (ACT == 2) vv = fmaxf(vv, 0.f);
            C[(size_t)m * ldc + n] = vv;
        }
    }
}

// ---------------- elementwise / reduction kernels ---------------------------

__global__ void conv16_k(const float* __restrict__ in, __half* __restrict__ out, size_t n) {
    size_t i = ((size_t)blockIdx.x * 256 + threadIdx.x) * 4;
    if (i < n) {
        float4 v = *(const float4*)(in + i);
        *(__half2*)(out + i)     = __floats2half2_rn(v.x, v.y);
        *(__half2*)(out + i + 2) = __floats2half2_rn(v.z, v.w);
    }
}

__global__ void addpos_k(float* __restrict__ h, __half* __restrict__ h16,
                         const float* __restrict__ pos) {
    size_t i = (size_t)blockIdx.x * 256 + threadIdx.x;
    if (i < (size_t)ROWS * NE) {
        float v = h[i] + pos[i % ((size_t)NS * NE)];
        h[i] = v;
        h16[i] = __float2half_rn(v);
    }
}

__global__ void zero_k(float* p, size_t n) {
    size_t i = (size_t)blockIdx.x * 256 + threadIdx.x;
    if (i < n) p[i] = 0.f;
}

__global__ void zerou_k(unsigned* p, int n) {
    int i = blockIdx.x * 256 + threadIdx.x;
    if (i < n) p[i] = 0u;   // 0 precedes ford(-inf): safe identity for ordered max
}

// grid-wide max of part[0..n) into ordered-uint cell
__global__ void maxredA_k(const float* __restrict__ part, int n, unsigned* __restrict__ out) {
    __shared__ float sh[256];
    int t = threadIdx.x;
    float m = -INFINITY;
    for (int i = blockIdx.x * 256 + t; i < n; i += gridDim.x * 256)
        m = fmaxf(m, part[i]);
    sh[t] = m; __syncthreads();
    for (int o = 128; o > 0; o >>= 1) { if (t < o) sh[t] = fmaxf(sh[t], sh[t + o]); __syncthreads(); }
    if (t == 0) atomicMax(out, ford(sh[0]));
}

__global__ void maxredB_k(const float* __restrict__ part, float* __restrict__ out) {
    __shared__ float sh[1024];
    int t = threadIdx.x, b = blockIdx.x;
    const float* p = part + (size_t)b * NS;
    float m = -INFINITY;
    for (int i = t; i < NS; i += 1024) m = fmaxf(m, p[i]);
    sh[t] = m; __syncthreads();
    for (int o = 512; o > 0; o >>= 1) { if (t < o) sh[t] = fmaxf(sh[t], sh[t + o]); __syncthreads(); }
    if (t == 0) out[b] = sh[0];
}

// pk: read fp32 logits, write fp16 exp(l - batchmax)/sqrt(M)
__global__ void phiexp_pk_k(const float* __restrict__ G, __half* __restrict__ G16,
                            const float* __restrict__ bmax, size_t n) {
    size_t i = (size_t)blockIdx.x * 256 + threadIdx.x;
    if (i < n) {
        float bm = bmax[i >> 19];
        G16[i] = __float2half_rn(expf(G[i] - bm) * 0.08838834764831845f);
    }
}

// z'[b,m] = sum_s pk16[b,s,m]
__global__ void colsum16_k(const __half* __restrict__ pk16, float* __restrict__ z) {
    int b = blockIdx.x, chunk = blockIdx.y, m = threadIdx.x;
    const __half* p = pk16 + (size_t)b * NS * NM + (size_t)chunk * 128 * NM + m;
    float s = 0.f;
    for (int i = 0; i < 128; i++) s += __half2float(p[(size_t)i * NM]);
    atomicAdd(&z[b * NM + m], s);
}

// inv[row] = G / (G*s + 1e-6),  G = exp(rowq-mxq + bmk-mx),  s = pq16 . z'
__global__ void den_k(const __half* __restrict__ pq16, const float* __restrict__ z,
                      const float* __restrict__ rowq, const unsigned* __restrict__ mxqo,
                      const float* __restrict__ bmk, const unsigned* __restrict__ mxko,
                      float* __restrict__ inv) {
    int warp = threadIdx.x >> 5, lane = threadIdx.x & 31;
    int row = blockIdx.x * 8 + warp;
    int b = row / NS;
    const __half* p = pq16 + (size_t)row * NM;
    const float* zz = z + b * NM;
    float s = 0.f;
#pragma unroll
    for (int j = 0; j < 4; j++)
        s = fmaf(__half2float(p[lane + 32 * j]), zz[lane + 32 * j], s);
#pragma unroll
    for (int o = 16; o > 0; o >>= 1) s += __shfl_xor_sync(0xffffffffu, s, o);
    if (lane == 0) {
        float mxq = funord(mxqo[0]);
        float mxk = funord(mxko[0]);
        float G = expf((rowq[row] - mxq) + (bmk[b] - mxk));
        inv[row] = G / (fmaf(G, s, 1e-6f));
    }
}

// LayerNorm over E=512; writes fp16 only
__global__ void ln_k(const float* __restrict__ in, __half* __restrict__ out16,
                     const float* __restrict__ g, const float* __restrict__ b) {
    int row = blockIdx.x, t = threadIdx.x;
    __shared__ float sh[256];
    const float* a = in + (size_t)row * NE;
    float x0 = a[t], x1 = a[t + 256];
    sh[t] = x0 + x1; __syncthreads();
    for (int o = 128; o > 0; o >>= 1) { if (t < o) sh[t] += sh[t + o]; __syncthreads(); }
    float mu = sh[0] * (1.f / NE);
    __syncthreads();
    float d0 = x0 - mu, d1 = x1 - mu;
    sh[t] = d0 * d0 + d1 * d1; __syncthreads();
    for (int o = 128; o > 0; o >>= 1) { if (t < o) sh[t] += sh[t + o]; __syncthreads(); }
    float rstd = rsqrtf(sh[0] * (1.f / NE) + 1e-5f);
    out16[(size_t)row * NE + t]       = __float2half_rn(d0 * rstd * g[t] + b[t]);
    out16[(size_t)row * NE + t + 256] = __float2half_rn(d1 * rstd * g[t + 256] + b[t + 256]);
}

// ---------------- host-side dispatch ----------------------------------------

template<int TRANS_A, int ACT, int WF32, int WF16, int MODE>
static void hgemm(const __half* A, int lda, size_t sA,
                  const __half* Bm, int ldb, size_t sB,
                  float* C, __half* C16, int ldc, size_t sC,
                  const float* bias, int M, int N, int K, int batch,
                  float* aux1 = nullptr, float* aux2 = nullptr)
{
    constexpr int ATILE_B = TRANS_A ? (BKH * T_HS * 2) : (128 * A_HS * 2);
    constexpr int SMEM = HG_STAGES * (ATILE_B + BKH * T_HS * 2);
    cudaFuncSetAttribute(hgemm_k<TRANS_A, ACT, WF32, WF16, MODE>,
                         cudaFuncAttributeMaxDynamicSharedMemorySize, SMEM);
    dim3 grid(N >> 7, M >> 7, batch);
    hgemm_k<TRANS_A, ACT, WF32, WF16, MODE><<<grid, 128, SMEM>>>(
        A, lda, sA, Bm, ldb, sB, C, C16, ldc, sC, bias, K, aux1, aux2);
}

// split-K variant: grid.y = k-chunks, M must be 128
static void hgemm_splitk_kv(const __half* A, const __half* Bm, float* C32)
{
    constexpr int ATILE_B = BKH * T_HS * 2;
    constexpr int SMEM = HG_STAGES * (ATILE_B + BKH * T_HS * 2);
    cudaFuncSetAttribute(hgemm_k<1, 0, 0, 0, 6>,
                         cudaFuncAttributeMaxDynamicSharedMemorySize, SMEM);
    dim3 grid(NE >> 7, KV_SPLIT, NB);
    hgemm_k<1, 0, 0, 0, 6><<<grid, 128, SMEM>>>(
        A, NM, (size_t)NS * NM, Bm, NE, (size_t)NS * NE,
        C32, nullptr, NE, (size_t)NM * NE, nullptr, NS / KV_SPLIT, nullptr, nullptr);
}

static void conv16(const float* in, __half* out, size_t n) {
    conv16_k<<<(unsigned)((n / 4 + 255) / 256), 256>>>(in, out, n);
}

extern "C" void kernel_launch(void* const* d_in, const int* in_sizes, int n_in,
                              void* d_out, int out_size)
{
    const float* x    = (const float*)d_in[0];
    const float* Wi   = (const float*)d_in[1];
    const float* bi   = (const float*)d_in[2];
    const float* pos  = (const float*)d_in[3];
    const float* Wq   = (const float*)d_in[4];
    const float* bq   = (const float*)d_in[5];
    const float* Wk   = (const float*)d_in[6];
    const float* bk   = (const float*)d_in[7];
    const float* Wv   = (const float*)d_in[8];
    const float* bv   = (const float*)d_in[9];
    const float* Wo   = (const float*)d_in[10];
    const float* bo   = (const float*)d_in[11];
    const float* R    = (const float*)d_in[12];
    const float* lng  = (const float*)d_in[13];
    const float* lnb  = (const float*)d_in[14];
    const float* W1   = (const float*)d_in[15];
    const float* b1   = (const float*)d_in[16];
    const float* W2   = (const float*)d_in[17];
    const float* b2   = (const float*)d_in[18];
    const float* Wr1  = (const float*)d_in[19];
    const float* br1  = (const float*)d_in[20];
    const float* Wr2  = (const float*)d_in[21];
    const float* br2  = (const float*)d_in[22];
    float* out = (float*)d_out;

    float *h,*k,*pk,*kv32,*z,*part,*rowq,*nq,*nk,*inv,*bmk,*r1;
    unsigned *mxo,*mxqo;
    __half *h16,*q16,*k16,*v16,*pq16,*pk16,*kv16,*ff16,*x16;
    __half *wi16,*wq16,*wk16,*wv16,*wo16,*r16,*w116,*w216;
    cudaGetSymbolAddress((void**)&h,  g_h);
    cudaGetSymbolAddress((void**)&k,  g_k);
    cudaGetSymbolAddress((void**)&pk, g_pk);
    cudaGetSymbolAddress((void**)&kv32, g_kv32);
    cudaGetSymbolAddress((void**)&z,  g_z);
    cudaGetSymbolAddress((void**)&part, g_part);
    cudaGetSymbolAddress((void**)&rowq, g_rowq);
    cudaGetSymbolAddress((void**)&nq, g_nq);
    cudaGetSymbolAddress((void**)&nk, g_nk);
    cudaGetSymbolAddress((void**)&inv, g_inv);
    cudaGetSymbolAddress((void**)&mxo, g_mxo);
    cudaGetSymbolAddress((void**)&mxqo, g_mxqo);
    cudaGetSymbolAddress((void**)&bmk, g_bmk);
    cudaGetSymbolAddress((void**)&r1, g_r1);
    cudaGetSymbolAddress((void**)&h16,  g_h16);
    cudaGetSymbolAddress((void**)&q16,  g_q16);
    cudaGetSymbolAddress((void**)&k16,  g_k16);
    cudaGetSymbolAddress((void**)&v16,  g_v16);
    cudaGetSymbolAddress((void**)&pq16, g_pq16);
    cudaGetSymbolAddress((void**)&pk16, g_pk16);
    cudaGetSymbolAddress((void**)&kv16, g_kv16);
    cudaGetSymbolAddress((void**)&ff16, g_ff16);
    cudaGetSymbolAddress((void**)&x16,  g_x16);
    cudaGetSymbolAddress((void**)&wi16, g_wi16);
    cudaGetSymbolAddress((void**)&wq16, g_wq16);
    cudaGetSymbolAddress((void**)&wk16, g_wk16);
    cudaGetSymbolAddress((void**)&wv16, g_wv16);
    cudaGetSymbolAddress((void**)&wo16, g_wo16);
    cudaGetSymbolAddress((void**)&r16,  g_r16);
    cudaGetSymbolAddress((void**)&w116, g_w116);
    cudaGetSymbolAddress((void**)&w216, g_w216);

    const size_t nHE = (size_t)ROWS * NE;
    const size_t nHM = (size_t)ROWS * NM;
    int ew_grid = (int)((nHE + 255) / 256);
    int pm_grid = (int)((nHM + 255) / 256);

    // ---- fp16 weight/input mirrors ----
    conv16(x,  x16, (size_t)ROWS * NDIN);
    conv16(Wi, wi16, (size_t)NDIN * NE);
    conv16(Wq, wq16, (size_t)NL * NE * NE);
    conv16(Wk, wk16, (size_t)NL * NE * NE);
    conv16(Wv, wv16, (size_t)NL * NE * NE);
    conv16(Wo, wo16, (size_t)NL * NE * NE);
    conv16(R,  r16,  (size_t)NL * NE * NM);
    conv16(W1, w116, (size_t)NL * NE * HID);
    conv16(W2, w216, (size_t)NL * HID * NE);

    // h = x @ Wi + bi ; then += pos (dual-write h16)
    hgemm<0,0,1,0,0>(x16, NDIN,0, wi16, NE,0, h, nullptr, NE,0, bi, ROWS, NE, NDIN, 1);
    addpos_k<<<ew_grid,256>>>(h, h16, pos);

    for (int i = 0; i < NL; i++) {
        const __half* wq_i = wq16 + (size_t)i*NE*NE;  const float* bq_i = bq + (size_t)i*NE;
        const __half* wk_i = wk16 + (size_t)i*NE*NE;  const float* bk_i = bk + (size_t)i*NE;
        const __half* wv_i = wv16 + (size_t)i*NE*NE;  const float* bv_i = bv + (size_t)i*NE;
        const __half* wo_i = wo16 + (size_t)i*NE*NE;  const float* bo_i = bo + (size_t)i*NE;
        const __half* r_i  = r16  + (size_t)i*NE*NM;
        const float* g_i  = lng + (size_t)i*NE;       const float* b_i  = lnb + (size_t)i*NE;
        const __half* w1_i = w116 + (size_t)i*NE*HID; const float* b1_i = b1 + (size_t)i*HID;
        const __half* w2_i = w216 + (size_t)i*HID*NE; const float* b2_i = b2 + (size_t)i*NE;

        // zero accumulators (sumsq + ordered-max cells)
        zero_k<<<ROWS/256,256>>>(nq, ROWS);
        zero_k<<<ROWS/256,256>>>(nk, ROWS);
        zerou_k<<<1,256>>>(mxo, 1);
        zerou_k<<<1,256>>>(mxqo, 1);

        // projections: Q/K with fused per-row sumsq, V plain
        hgemm<0,0,0,1,1>(h16, NE,0, wq_i, NE,0, nullptr, q16, NE,0, bq_i, ROWS, NE, NE, 1, nq);
        hgemm<0,0,0,1,1>(h16, NE,0, wk_i, NE,0, nullptr, k16, NE,0, bk_i, ROWS, NE, NE, 1, nk);
        hgemm<0,0,0,1,0>(h16, NE,0, wv_i, NE,0, nullptr, v16, NE,0, bv_i, ROWS, NE, NE, 1);

        // phi-q FULLY FUSED: logits + rowmax + exp -> pq16 (row-normalized)
        hgemm<0,0,0,0,5>(q16, NE,0, r_i, NM,0, nullptr, pq16, NM,0, nullptr, ROWS, NM, NE, 1, nq, rowq);
        maxredA_k<<<256,256>>>(rowq, ROWS, mxqo);

        // phi-k: fused logits + rowmax (logits fp32 in pk, rowmax in part)
        hgemm<0,0,1,0,2>(k16, NE,0, r_i, NM,0, pk, nullptr, NM,0, nullptr, ROWS, NM, NE, 1, nk, part);
        maxredA_k<<<256,256>>>(part, ROWS, mxo);
        maxredB_k<<<NB,1024>>>(part, bmk);
        phiexp_pk_k<<<pm_grid,256>>>(pk, pk16, bmk, nHM);

        // kv[b] = pk16[b]^T @ v16[b]  — split-K, fp32 atomic accumulation
        zero_k<<<((size_t)NB*NM*NE+255)/256,256>>>(kv32, (size_t)NB*NM*NE);
        hgemm_splitk_kv(pk16, v16, kv32);
        conv16(kv32, kv16, (size_t)NB*NM*NE);

        // z'[b] = sum_s pk16[b,s,:]
        zero_k<<<(NB*NM+255)/256,256>>>(z, NB*NM);
        colsum16_k<<<dim3(NB,32),128>>>(pk16, z);

        // inv[row] = G / (G*(pq16.z') + 1e-6)
        den_k<<<ROWS/8,256>>>(pq16, z, rowq, mxqo, bmk, mxo, inv);

        // num GEMM with fused row scaling -> q16
        hgemm<0,0,0,1,3>(pq16, NM, (size_t)NS*NM, kv16, NE, (size_t)NM*NE,
                         nullptr, q16, NE, (size_t)NS*NE, nullptr, NS, NE, NM, NB, inv);

        // a -> k (fp32, LN input)
        hgemm<0,0,1,0,0>(q16, NE,0, wo_i, NE,0, k, nullptr, NE,0, bo_i, ROWS, NE, NE, 1);

        // y -> v16 (LayerNorm)
        ln_k<<<ROWS,256>>>(k, v16, g_i, b_i);

        // ff1 = gelu(y @ W1 + b1) -> ff16
        hgemm<0,1,0,1,0>(v16, NE,0, w1_i, HID,0, nullptr, ff16, HID,0, b1_i, ROWS, HID, NE, 1);
        // ff2 with fused residual: h = ff2 + b2 + h ; dual-write h16
        hgemm<0,0,1,1,4>(ff16, HID,0, w2_i, NE,0, h, h16, NE,0, b2_i, ROWS, NE, HID, 1);
    }

    // head: pooled = h[:,0,:] — tiny, fp32 path
    {
        dim3 g1((256 + BN - 1) / BN, (NB + BM - 1) / BM);
        gemm_k<2><<<g1, 256>>>(h, NS*NE, Wr1, 256, r1, 256, br1, NB, 256, NE);
        dim3 g2(1, 1);
        gemm_k<0><<<g2, 256>>>(r1, 256, Wr2, 1, out, 1, br2, NB, 1, 256);
    }
}

// round 15
// speedup vs baseline: 1.0110x; 1.0110x over previous
#include <cuda_runtime.h>
#include <cuda_fp16.h>
#include <math.h>
#include <stdint.h>

#define NB 16
#define NS 4096
#define NDIN 64
#define NE 512
#define NM 128
#define NL 4
#define ROWS (NB*NS)        /* 65536 */
#define HID (4*NE)          /* 2048 */
#define KV_SPLIT 8

// ---------------- scratch (device globals; no allocations allowed) ----------
__device__ float g_h [(size_t)ROWS*NE];
__device__ float g_k [(size_t)ROWS*NE];
__device__ float g_pk[(size_t)ROWS*NM];   // pk logits (fp32)
__device__ float g_kv32[(size_t)NB*NM*NE];
__device__ float g_z [NB*NM];
__device__ float g_part [ROWS];   // per-row max (pk pass)
__device__ float g_rowq [ROWS];   // per-row max for pq
__device__ float g_nq  [ROWS];    // per-row sum-of-squares (q)
__device__ float g_nk  [ROWS];    // per-row sum-of-squares (k)
__device__ float g_inv [ROWS];    // per-row 1/den factor
__device__ unsigned g_mxo [1];    // global max (pk), ordered-uint encoding
__device__ unsigned g_mxqo[1];    // global max (pq), ordered-uint encoding
__device__ float g_bmk [NB];      // per-batch max (pk)
__device__ float g_r1[16*256];

// fp16 mirrors
__device__ __half g_h16 [(size_t)ROWS*NE];
__device__ __half g_q16 [(size_t)ROWS*NE];
__device__ __half g_k16 [(size_t)ROWS*NE];
__device__ __half g_v16 [(size_t)ROWS*NE];
__device__ __half g_pq16[(size_t)ROWS*NM];
__device__ __half g_pk16[(size_t)ROWS*NM];
__device__ __half g_kv16[(size_t)NB*NM*NE];
__device__ __half g_ff16[(size_t)ROWS*HID];
__device__ __half g_x16 [(size_t)ROWS*NDIN];
__device__ __half g_wi16[NDIN*NE];
__device__ __half g_wq16[(size_t)NL*NE*NE];
__device__ __half g_wk16[(size_t)NL*NE*NE];
__device__ __half g_wv16[(size_t)NL*NE*NE];
__device__ __half g_wo16[(size_t)NL*NE*NE];
__device__ __half g_r16 [(size_t)NL*NE*NM];
__device__ __half g_w116[(size_t)NL*NE*HID];
__device__ __half g_w216[(size_t)NL*HID*NE];

// ================= helpers =================
__device__ __forceinline__ uint32_t smem_u32(const void* p) {
    uint32_t r;
    asm("{ .reg .u64 t; cvta.to.shared.u64 t, %1; cvt.u32.u64 %0, t; }" : "=r"(r) : "l"(p));
    return r;
}
__device__ __forceinline__ void cp_async16(uint32_t saddr, const void* g) {
    asm volatile("cp.async.cg.shared.global [%0], [%1], 16;" :: "r"(saddr), "l"(g));
}
__device__ __forceinline__ void ldsm_x4(uint32_t r[4], uint32_t addr) {
    asm volatile("ldmatrix.sync.aligned.m8n8.x4.shared.b16 {%0,%1,%2,%3}, [%4];"
                 : "=r"(r[0]), "=r"(r[1]), "=r"(r[2]), "=r"(r[3]) : "r"(addr));
}
__device__ __forceinline__ void ldsm_x4_t(uint32_t r[4], uint32_t addr) {
    asm volatile("ldmatrix.sync.aligned.m8n8.x4.trans.shared.b16 {%0,%1,%2,%3}, [%4];"
                 : "=r"(r[0]), "=r"(r[1]), "=r"(r[2]), "=r"(r[3]) : "r"(addr));
}
__device__ __forceinline__ void mma_f16(float c[4], const uint32_t a[4], const uint32_t b[2]) {
    asm volatile(
        "mma.sync.aligned.m16n8k16.row.col.f32.f16.f16.f32 "
        "{%0,%1,%2,%3}, {%4,%5,%6,%7}, {%8,%9}, {%0,%1,%2,%3};"
        : "+f"(c[0]), "+f"(c[1]), "+f"(c[2]), "+f"(c[3])
        : "r"(a[0]), "r"(a[1]), "r"(a[2]), "r"(a[3]), "r"(b[0]), "r"(b[1]));
}
// monotonic float<->uint encoding: a<=b (float) <=> ford(a)<=ford(b) (uint)
__device__ __forceinline__ unsigned ford(float f) {
    unsigned u = __float_as_uint(f);
    return (u & 0x80000000u) ? ~u : (u | 0x80000000u);
}
__device__ __forceinline__ float funord(unsigned u) {
    return __uint_as_float((u & 0x80000000u) ? (u & 0x7fffffffu) : ~u);
}

// ================= fp16 mma GEMM with fused epilogues =================
// 128 threads / 4 warps; CTA tile 128x128; warp tile 64x64; BK=32, 4 stages.
// MODE 0: plain; MODE 1: SUMSQ; MODE 2: PHI; MODE 3: SCALEROW; MODE 4: RESID;
// MODE 5: PHIEXP; MODE 6: SPLITK (blockIdx.y = k-chunk, atomicAdd fp32 into C).

#define BKH 32
#define A_HS 40
#define T_HS 136
#define HG_STAGES 4

template<int TRANS_A>
__device__ __forceinline__ void h_fill(const __half* __restrict__ A, int lda,
                                       const __half* __restrict__ B, int ldb,
                                       int m0, int n0, int kof,
                                       uint32_t sa, uint32_t sb, int tid) {
    if (!TRANS_A) {
#pragma unroll
        for (int i = 0; i < 4; i++) {
            int lin = (i << 7) + tid;
            int row = lin >> 2, c = lin & 3;
            cp_async16(sa + (uint32_t)(row * A_HS + (c << 3)) * 2,
                       A + (size_t)(m0 + row) * lda + kof + (c << 3));
        }
    } else {
#pragma unroll
        for (int i = 0; i < 4; i++) {
            int lin = (i << 7) + tid;
            int row = lin >> 4, c = lin & 15;
            cp_async16(sa + (uint32_t)(row * T_HS + (c << 3)) * 2,
                       A + (size_t)(kof + row) * lda + m0 + (c << 3));
        }
    }
#pragma unroll
    for (int i = 0; i < 4; i++) {
        int lin = (i << 7) + tid;
        int row = lin >> 4, c = lin & 15;
        cp_async16(sb + (uint32_t)(row * T_HS + (c << 3)) * 2,
                   B + (size_t)(kof + row) * ldb + n0 + (c << 3));
    }
}

template<int TRANS_A, int ACT, int WF32, int WF16, int MODE>
__global__ __launch_bounds__(128, 2)
void hgemm_k(const __half* __restrict__ A, int lda, size_t sAs,
             const __half* __restrict__ B, int ldb, size_t sBs,
             float* __restrict__ C, __half* __restrict__ C16, int ldc, size_t sCs,
             const float* __restrict__ bias, int K,
             float* __restrict__ aux1, float* __restrict__ aux2)
{
    constexpr int ATILE_B = TRANS_A ? (BKH * T_HS * 2) : (128 * A_HS * 2);
    constexpr int STAGE_B = ATILE_B + BKH * T_HS * 2;

    extern __shared__ __half hsm[];
    uint32_t smb = smem_u32(hsm);
    int tid = threadIdx.x;
    int wid = tid >> 5, lane = tid & 31;
    int group = lane >> 3, lr = lane & 7;
    int g = lane >> 2, t4 = lane & 3;

    A += (size_t)blockIdx.z * sAs;
    B += (size_t)blockIdx.z * sBs;
    int m0 = (MODE == 6) ? 0 : (blockIdx.y << 7);
    int kb = (MODE == 6) ? (blockIdx.y * K) : 0;   // k-chunk base for split-K
    int n0 = blockIdx.x << 7;
    int wm = wid & 1, wn = wid >> 1;

    float c[4][8][4];
#pragma unroll
    for (int a = 0; a < 4; a++)
#pragma unroll
        for (int b = 0; b < 8; b++)
#pragma unroll
            for (int r = 0; r < 4; r++) c[a][b][r] = 0.f;

    int nk = K >> 5;

#pragma unroll
    for (int s = 0; s < HG_STAGES - 1; s++) {
        if (s < nk) {
            uint32_t sa = smb + (uint32_t)s * STAGE_B;
            h_fill<TRANS_A>(A, lda, B, ldb, m0, n0, kb + (s << 5), sa, sa + ATILE_B, tid);
        }
        asm volatile("cp.async.commit_group;");
    }

    for (int kt = 0; kt < nk; kt++) {
        asm volatile("cp.async.wait_group %0;" :: "n"(HG_STAGES - 2));
        __syncthreads();

        int nxt = kt + HG_STAGES - 1;
        if (nxt < nk) {
            uint32_t sa = smb + (uint32_t)(nxt & (HG_STAGES - 1)) * STAGE_B;
            h_fill<TRANS_A>(A, lda, B, ldb, m0, n0, kb + (nxt << 5), sa, sa + ATILE_B, tid);
        }
        asm volatile("cp.async.commit_group;");

        uint32_t sa = smb + (uint32_t)(kt & (HG_STAGES - 1)) * STAGE_B;
        uint32_t sb = sa + ATILE_B;
#pragma unroll
        for (int ks = 0; ks < 2; ks++) {
            uint32_t af[4][4];
#pragma unroll
            for (int mi = 0; mi < 4; mi++) {
                uint32_t addr;
                if (!TRANS_A) {
                    int arow = (wm << 6) + (mi << 4) + ((group & 1) << 3) + lr;
                    int acol = (ks << 4) + ((group >> 1) << 3);
                    addr = sa + (uint32_t)(arow * A_HS + acol) * 2;
                    ldsm_x4(af[mi], addr);
                } else {
                    int krow = (ks << 4) + ((group >> 1) << 3) + lr;
                    int mcol = (wm << 6) + (mi << 4) + ((group & 1) << 3);
                    addr = sa + (uint32_t)(krow * T_HS + mcol) * 2;
                    ldsm_x4_t(af[mi], addr);
                }
            }
            uint32_t bf[4][4];
#pragma unroll
            for (int np = 0; np < 4; np++) {
                int krow = (ks << 4) + ((group & 1) << 3) + lr;
                int ncol = (wn << 6) + (np << 4) + ((group >> 1) << 3);
                ldsm_x4_t(bf[np], sb + (uint32_t)(krow * T_HS + ncol) * 2);
            }
#pragma unroll
            for (int mi = 0; mi < 4; mi++)
#pragma unroll
                for (int ni = 0; ni < 8; ni++)
                    mma_f16(c[mi][ni], af[mi], &bf[ni >> 1][(ni & 1) << 1]);
        }
    }

    // ---- epilogue ----
    if (MODE == 2 || MODE == 5) __syncthreads();     // smem reused as logit stage
    float* stage = (float*)hsm;
    int auxrows = (int)(sCs / (size_t)ldc);
    const float GK = 0.7071067811865476f;
    const float PSCALE = 0.21022410381342865f;   // 512^-0.25
    const float PS2    = 0.02209708691207961f;   // 0.5 * 512^-0.5
#pragma unroll
    for (int mi = 0; mi < 4; mi++) {
        int r = (wm << 6) + (mi << 4) + g;
        size_t rowoff0 = (size_t)blockIdx.z * sCs + (size_t)(m0 + r) * ldc;
        size_t rowoff1 = rowoff0 + (size_t)8 * ldc;
        int ar0 = blockIdx.z * auxrows + m0 + r;
        int ar1 = ar0 + 8;
        float n2a = 0.f, n2b = 0.f, iv0 = 0.f, iv1 = 0.f;
        if (MODE == 2 || MODE == 5) { n2a = aux1[ar0]; n2b = aux1[ar1]; }
        if (MODE == 3) { iv0 = aux1[ar0]; iv1 = aux1[ar1]; }
        float ssq0 = 0.f, ssq1 = 0.f;
#pragma unroll
        for (int ni = 0; ni < 8; ni++) {
            int nn = n0 + (wn << 6) + (ni << 3) + (t4 << 1);
            float v0 = c[mi][ni][0], v1 = c[mi][ni][1];
            float v2 = c[mi][ni][2], v3 = c[mi][ni][3];
            if (bias) {
                float b0 = __ldg(bias + nn), b1 = __ldg(bias + nn + 1);
                v0 += b0; v1 += b1; v2 += b0; v3 += b1;
            }
            if (ACT == 1) {
                v0 = 0.5f * v0 * (1.f + erff(v0 * GK));
                v1 = 0.5f * v1 * (1.f + erff(v1 * GK));
                v2 = 0.5f * v2 * (1.f + erff(v2 * GK));
                v3 = 0.5f * v3 * (1.f + erff(v3 * GK));
            }
            if (MODE == 1) {
                ssq0 += v0 * v0 + v1 * v1;
                ssq1 += v2 * v2 + v3 * v3;
            }
            if (MODE == 2 || MODE == 5) {
                int rl = (wm << 6) + (mi << 4) + g;
                v0 = fmaf(v0, PSCALE, -PS2 * n2a);
                v1 = fmaf(v1, PSCALE, -PS2 * n2a);
                v2 = fmaf(v2, PSCALE, -PS2 * n2b);
                v3 = fmaf(v3, PSCALE, -PS2 * n2b);
                int nl = (wn << 6) + (ni << 3) + (t4 << 1);
                stage[rl * 132 + nl] = v0;       stage[rl * 132 + nl + 1] = v1;
                stage[(rl + 8) * 132 + nl] = v2; stage[(rl + 8) * 132 + nl + 1] = v3;
            }
            if (MODE == 3) { v0 *= iv0; v1 *= iv0; v2 *= iv1; v3 *= iv1; }
            if (MODE == 4) {
                float2 r0 = *(float2*)(C + rowoff0 + nn);
                float2 r1 = *(float2*)(C + rowoff1 + nn);
                v0 += r0.x; v1 += r0.y; v2 += r1.x; v3 += r1.y;
            }
            if (MODE == 6) {
                atomicAdd(C + rowoff0 + nn, v0);
                atomicAdd(C + rowoff0 + nn + 1, v1);
                atomicAdd(C + rowoff1 + nn, v2);
                atomicAdd(C + rowoff1 + nn + 1, v3);
            }
            if (WF32) {
                *(float2*)(C + rowoff0 + nn) = make_float2(v0, v1);
                *(float2*)(C + rowoff1 + nn) = make_float2(v2, v3);
            }
            if (WF16) {
                *(__half2*)(C16 + rowoff0 + nn) = __floats2half2_rn(v0, v1);
                *(__half2*)(C16 + rowoff1 + nn) = __floats2half2_rn(v2, v3);
            }
        }
        if (MODE == 1) {
            ssq0 += __shfl_xor_sync(0xffffffffu, ssq0, 1);
            ssq0 += __shfl_xor_sync(0xffffffffu, ssq0, 2);
            ssq1 += __shfl_xor_sync(0xffffffffu, ssq1, 1);
            ssq1 += __shfl_xor_sync(0xffffffffu, ssq1, 2);
            if (t4 == 0) {
                atomicAdd(&aux1[ar0], ssq0);
                atomicAdd(&aux1[ar1], ssq1);
            }
        }
    }
    if (MODE == 2 || MODE == 5) {
        __syncthreads();
        int rr = tid;                        // one thread per row (128)
        const float* rp = stage + rr * 132;
        float m = -INFINITY;
#pragma unroll
        for (int j = 0; j < 128; j++) m = fmaxf(m, rp[j]);
        aux2[m0 + rr] = m;
        if (MODE == 5) {
            __half* dst = C16 + (size_t)(m0 + rr) * ldc;
#pragma unroll
            for (int j = 0; j < 128; j += 2) {
                float e0 = expf(rp[j]     - m) * 0.08838834764831845f;
                float e1 = expf(rp[j + 1] - m) * 0.08838834764831845f;
                *(__half2*)(dst + j) = __floats2half2_rn(e0, e1);
            }
        }
    }
}

// ================= fp32 fallback SGEMM (head only) =================
#define BM 128
#define BN 128
#define BK 8

template<int ACT>
__global__ __launch_bounds__(256)
void gemm_k(const float* __restrict__ A, int lda,
            const float* __restrict__ Bm, int ldb,
            float* __restrict__ C, int ldc,
            const float* __restrict__ bias,
            int M, int N, int K)
{
    int m0 = blockIdx.y * BM;
    int n0 = blockIdx.x * BN;

    __shared__ float As[BK][BM];
    __shared__ float Bs[BK][BN];

    int tid = threadIdx.x;
    int tx = tid & 15, ty = tid >> 4;

    float acc[8][8];
#pragma unroll
    for (int i = 0; i < 8; i++)
#pragma unroll
        for (int j = 0; j < 8; j++) acc[i][j] = 0.f;

    float ar[8], br[8];

    for (int k0 = 0; k0 < K; k0 += BK) {
        {
            int m  = tid >> 1;
            int kk = (tid & 1) * 4;
            bool mok = (m0 + m) < M;
            const float* src = A + (size_t)(m0 + m) * lda + k0 + kk;
#pragma unroll
            for (int i = 0; i < 4; i++)
                As[kk + i][m] = mok ? src[i] : 0.f;
        }
        {
            int k = tid >> 5;
            int n = (tid & 31) * 4;
            const float* src = Bm + (size_t)(k0 + k) * ldb + n0 + n;
#pragma unroll
            for (int i = 0; i < 4; i++) {
                float vv = 0.f;
                if (n0 + n + i < N) vv = src[i];
                Bs[k][n + i] = vv;
            }
        }
        __syncthreads();
#pragma unroll
        for (int k = 0; k < BK; k++) {
            *(float4*)&ar[0] = *(float4*)&As[k][ty * 4];
            *(float4*)&ar[4] = *(float4*)&As[k][64 + ty * 4];
            *(float4*)&br[0] = *(float4*)&Bs[k][tx * 4];
            *(float4*)&br[4] = *(float4*)&Bs[k][64 + tx * 4];
#pragma unroll
            for (int i = 0; i < 8; i++)
#pragma unroll
                for (int j = 0; j < 8; j++)
                    acc[i][j] = fmaf(ar[i], br[j], acc[i][j]);
        }
        __syncthreads();
    }

#pragma unroll
    for (int i = 0; i < 8; i++) {
        int m = m0 + ((i < 4) ? (ty * 4 + i) : (64 + ty * 4 + i - 4));
        if (m >= M) continue;
#pragma unroll
        for (int j = 0; j < 8; j++) {
            int n = n0 + ((j < 4) ? (tx * 4 + j) : (64 + tx * 4 + j - 4));
            if (n >= N) continue;
            float vv = acc[i][j];
            if (bias) vv += bias[n];
            if (ACT == 2) vv = fmaxf(vv, 0.f);
            C[(size_t)m * ldc + n] = vv;
        }
    }
}

// ---------------- elementwise / reduction kernels ---------------------------

__global__ void conv16_k(const float* __restrict__ in, __half* __restrict__ out, size_t n) {
    size_t i = ((size_t)blockIdx.x * 256 + threadIdx.x) * 4;
    if (i < n) {
        float4 v = *(const float4*)(in + i);
        *(__half2*)(out + i)     = __floats2half2_rn(v.x, v.y);
        *(__half2*)(out + i + 2) = __floats2half2_rn(v.z, v.w);
    }
}

__global__ void addpos_k(float* __restrict__ h, __half* __restrict__ h16,
                         const float* __restrict__ pos) {
    size_t i = (size_t)blockIdx.x * 256 + threadIdx.x;
    if (i < (size_t)ROWS * NE) {
        float v = h[i] + pos[i % ((size_t)NS * NE)];
        h[i] = v;
        h16[i] = __float2half_rn(v);
    }
}

__global__ void zero_k(float* p, size_t n) {
    size_t i = (size_t)blockIdx.x * 256 + threadIdx.x;
    if (i < n) p[i] = 0.f;
}

__global__ void zerou_k(unsigned* p, int n) {
    int i = blockIdx.x * 256 + threadIdx.x;
    if (i < n) p[i] = 0u;   // 0 precedes ford(-inf): safe identity for ordered max
}

// grid-wide max of part[0..n) into ordered-uint cell
__global__ void maxredA_k(const float* __restrict__ part, int n, unsigned* __restrict__ out) {
    __shared__ float sh[256];
    int t = threadIdx.x;
    float m = -INFINITY;
    for (int i = blockIdx.x * 256 + t; i < n; i += gridDim.x * 256)
        m = fmaxf(m, part[i]);
    sh[t] = m; __syncthreads();
    for (int o = 128; o > 0; o >>= 1) { if (t < o) sh[t] = fmaxf(sh[t], sh[t + o]); __syncthreads(); }
    if (t == 0) atomicMax(out, ford(sh[0]));
}

__global__ void maxredB_k(const float* __restrict__ part, float* __restrict__ out) {
    __shared__ float sh[1024];
    int t = threadIdx.x, b = blockIdx.x;
    const float* p = part + (size_t)b * NS;
    float m = -INFINITY;
    for (int i = t; i < NS; i += 1024) m = fmaxf(m, p[i]);
    sh[t] = m; __syncthreads();
    for (int o = 512; o > 0; o >>= 1) { if (t < o) sh[t] = fmaxf(sh[t], sh[t + o]); __syncthreads(); }
    if (t == 0) out[b] = sh[0];
}

// pk: read fp32 logits, write fp16 exp(l - batchmax)/sqrt(M)
__global__ void phiexp_pk_k(const float* __restrict__ G, __half* __restrict__ G16,
                            const float* __restrict__ bmax, size_t n) {
    size_t i = (size_t)blockIdx.x * 256 + threadIdx.x;
    if (i < n) {
        float bm = bmax[i >> 19];
        G16[i] = __float2half_rn(expf(G[i] - bm) * 0.08838834764831845f);
    }
}

// z'[b,m] = sum_s pk16[b,s,m]
__global__ void colsum16_k(const __half* __restrict__ pk16, float* __restrict__ z) {
    int b = blockIdx.x, chunk = blockIdx.y, m = threadIdx.x;
    const __half* p = pk16 + (size_t)b * NS * NM + (size_t)chunk * 128 * NM + m;
    float s = 0.f;
    for (int i = 0; i < 128; i++) s += __half2float(p[(size_t)i * NM]);
    atomicAdd(&z[b * NM + m], s);
}

// inv[row] = G / (G*s + 1e-6),  G = exp(rowq-mxq + bmk-mx),  s = pq16 . z'
__global__ void den_k(const __half* __restrict__ pq16, const float* __restrict__ z,
                      const float* __restrict__ rowq, const unsigned* __restrict__ mxqo,
                      const float* __restrict__ bmk, const unsigned* __restrict__ mxko,
                      float* __restrict__ inv) {
    int warp = threadIdx.x >> 5, lane = threadIdx.x & 31;
    int row = blockIdx.x * 8 + warp;
    int b = row / NS;
    const __half* p = pq16 + (size_t)row * NM;
    const float* zz = z + b * NM;
    float s = 0.f;
#pragma unroll
    for (int j = 0; j < 4; j++)
        s = fmaf(__half2float(p[lane + 32 * j]), zz[lane + 32 * j], s);
#pragma unroll
    for (int o = 16; o > 0; o >>= 1) s += __shfl_xor_sync(0xffffffffu, s, o);
    if (lane == 0) {
        float mxq = funord(mxqo[0]);
        float mxk = funord(mxko[0]);
        float G = expf((rowq[row] - mxq) + (bmk[b] - mxk));
        inv[row] = G / (fmaf(G, s, 1e-6f));
    }
}

// LayerNorm over E=512; writes fp16 only
__global__ void ln_k(const float* __restrict__ in, __half* __restrict__ out16,
                     const float* __restrict__ g, const float* __restrict__ b) {
    int row = blockIdx.x, t = threadIdx.x;
    __shared__ float sh[256];
    const float* a = in + (size_t)row * NE;
    float x0 = a[t], x1 = a[t + 256];
    sh[t] = x0 + x1; __syncthreads();
    for (int o = 128; o > 0; o >>= 1) { if (t < o) sh[t] += sh[t + o]; __syncthreads(); }
    float mu = sh[0] * (1.f / NE);
    __syncthreads();
    float d0 = x0 - mu, d1 = x1 - mu;
    sh[t] = d0 * d0 + d1 * d1; __syncthreads();
    for (int o = 128; o > 0; o >>= 1) { if (t < o) sh[t] += sh[t + o]; __syncthreads(); }
    float rstd = rsqrtf(sh[0] * (1.f / NE) + 1e-5f);
    out16[(size_t)row * NE + t]       = __float2half_rn(d0 * rstd * g[t] + b[t]);
    out16[(size_t)row * NE + t + 256] = __float2half_rn(d1 * rstd * g[t + 256] + b[t + 256]);
}

// ---------------- host-side dispatch ----------------------------------------

template<int TRANS_A, int ACT, int WF32, int WF16, int MODE>
static void hgemm(const __half* A, int lda, size_t sA,
                  const __half* Bm, int ldb, size_t sB,
                  float* C, __half* C16, int ldc, size_t sC,
                  const float* bias, int M, int N, int K, int batch,
                  float* aux1 = nullptr, float* aux2 = nullptr)
{
    constexpr int ATILE_B = TRANS_A ? (BKH * T_HS * 2) : (128 * A_HS * 2);
    constexpr int SMEM = HG_STAGES * (ATILE_B + BKH * T_HS * 2);
    cudaFuncSetAttribute(hgemm_k<TRANS_A, ACT, WF32, WF16, MODE>,
                         cudaFuncAttributeMaxDynamicSharedMemorySize, SMEM);
    dim3 grid(N >> 7, M >> 7, batch);
    hgemm_k<TRANS_A, ACT, WF32, WF16, MODE><<<grid, 128, SMEM>>>(
        A, lda, sA, Bm, ldb, sB, C, C16, ldc, sC, bias, K, aux1, aux2);
}

// split-K variant: grid.y = k-chunks, M must be 128
static void hgemm_splitk_kv(const __half* A, const __half* Bm, float* C32)
{
    constexpr int ATILE_B = BKH * T_HS * 2;
    constexpr int SMEM = HG_STAGES * (ATILE_B + BKH * T_HS * 2);
    cudaFuncSetAttribute(hgemm_k<1, 0, 0, 0, 6>,
                         cudaFuncAttributeMaxDynamicSharedMemorySize, SMEM);
    dim3 grid(NE >> 7, KV_SPLIT, NB);
    hgemm_k<1, 0, 0, 0, 6><<<grid, 128, SMEM>>>(
        A, NM, (size_t)NS * NM, Bm, NE, (size_t)NS * NE,
        C32, nullptr, NE, (size_t)NM * NE, nullptr, NS / KV_SPLIT, nullptr, nullptr);
}

static void conv16(const float* in, __half* out, size_t n) {
    conv16_k<<<(unsigned)((n / 4 + 255) / 256), 256>>>(in, out, n);
}

extern "C" void kernel_launch(void* const* d_in, const int* in_sizes, int n_in,
                              void* d_out, int out_size)
{
    const float* x    = (const float*)d_in[0];
    const float* Wi   = (const float*)d_in[1];
    const float* bi   = (const float*)d_in[2];
    const float* pos  = (const float*)d_in[3];
    const float* Wq   = (const float*)d_in[4];
    const float* bq   = (const float*)d_in[5];
    const float* Wk   = (const float*)d_in[6];
    const float* bk   = (const float*)d_in[7];
    const float* Wv   = (const float*)d_in[8];
    const float* bv   = (const float*)d_in[9];
    const float* Wo   = (const float*)d_in[10];
    const float* bo   = (const float*)d_in[11];
    const float* R    = (const float*)d_in[12];
    const float* lng  = (const float*)d_in[13];
    const float* lnb  = (const float*)d_in[14];
    const float* W1   = (const float*)d_in[15];
    const float* b1   = (const float*)d_in[16];
    const float* W2   = (const float*)d_in[17];
    const float* b2   = (const float*)d_in[18];
    const float* Wr1  = (const float*)d_in[19];
    const float* br1  = (const float*)d_in[20];
    const float* Wr2  = (const float*)d_in[21];
    const float* br2  = (const float*)d_in[22];
    float* out = (float*)d_out;

    float *h,*k,*pk,*kv32,*z,*part,*rowq,*nq,*nk,*inv,*bmk,*r1;
    unsigned *mxo,*mxqo;
    __half *h16,*q16,*k16,*v16,*pq16,*pk16,*kv16,*ff16,*x16;
    __half *wi16,*wq16,*wk16,*wv16,*wo16,*r16,*w116,*w216;
    cudaGetSymbolAddress((void**)&h,  g_h);
    cudaGetSymbolAddress((void**)&k,  g_k);
    cudaGetSymbolAddress((void**)&pk, g_pk);
    cudaGetSymbolAddress((void**)&kv32, g_kv32);
    cudaGetSymbolAddress((void**)&z,  g_z);
    cudaGetSymbolAddress((void**)&part, g_part);
    cudaGetSymbolAddress((void**)&rowq, g_rowq);
    cudaGetSymbolAddress((void**)&nq, g_nq);
    cudaGetSymbolAddress((void**)&nk, g_nk);
    cudaGetSymbolAddress((void**)&inv, g_inv);
    cudaGetSymbolAddress((void**)&mxo, g_mxo);
    cudaGetSymbolAddress((void**)&mxqo, g_mxqo);
    cudaGetSymbolAddress((void**)&bmk, g_bmk);
    cudaGetSymbolAddress((void**)&r1, g_r1);
    cudaGetSymbolAddress((void**)&h16,  g_h16);
    cudaGetSymbolAddress((void**)&q16,  g_q16);
    cudaGetSymbolAddress((void**)&k16,  g_k16);
    cudaGetSymbolAddress((void**)&v16,  g_v16);
    cudaGetSymbolAddress((void**)&pq16, g_pq16);
    cudaGetSymbolAddress((void**)&pk16, g_pk16);
    cudaGetSymbolAddress((void**)&kv16, g_kv16);
    cudaGetSymbolAddress((void**)&ff16, g_ff16);
    cudaGetSymbolAddress((void**)&x16,  g_x16);
    cudaGetSymbolAddress((void**)&wi16, g_wi16);
    cudaGetSymbolAddress((void**)&wq16, g_wq16);
    cudaGetSymbolAddress((void**)&wk16, g_wk16);
    cudaGetSymbolAddress((void**)&wv16, g_wv16);
    cudaGetSymbolAddress((void**)&wo16, g_wo16);
    cudaGetSymbolAddress((void**)&r16,  g_r16);
    cudaGetSymbolAddress((void**)&w116, g_w116);
    cudaGetSymbolAddress((void**)&w216, g_w216);

    const size_t nHE = (size_t)ROWS * NE;
    const size_t nHM = (size_t)ROWS * NM;
    int ew_grid = (int)((nHE + 255) / 256);
    int pm_grid = (int)((nHM + 255) / 256);

    // ---- fp16 weight/input mirrors ----
    conv16(x,  x16, (size_t)ROWS * NDIN);
    conv16(Wi, wi16, (size_t)NDIN * NE);
    conv16(Wq, wq16, (size_t)NL * NE * NE);
    conv16(Wk, wk16, (size_t)NL * NE * NE);
    conv16(Wv, wv16, (size_t)NL * NE * NE);
    conv16(Wo, wo16, (size_t)NL * NE * NE);
    conv16(R,  r16,  (size_t)NL * NE * NM);
    conv16(W1, w116, (size_t)NL * NE * HID);
    conv16(W2, w216, (size_t)NL * HID * NE);

    // h = x @ Wi + bi ; then += pos (dual-write h16)
    hgemm<0,0,1,0,0>(x16, NDIN,0, wi16, NE,0, h, nullptr, NE,0, bi, ROWS, NE, NDIN, 1);
    addpos_k<<<ew_grid,256>>>(h, h16, pos);

    for (int i = 0; i < NL; i++) {
        const __half* wq_i = wq16 + (size_t)i*NE*NE;  const float* bq_i = bq + (size_t)i*NE;
        const __half* wk_i = wk16 + (size_t)i*NE*NE;  const float* bk_i = bk + (size_t)i*NE;
        const __half* wv_i = wv16 + (size_t)i*NE*NE;  const float* bv_i = bv + (size_t)i*NE;
        const __half* wo_i = wo16 + (size_t)i*NE*NE;  const float* bo_i = bo + (size_t)i*NE;
        const __half* r_i  = r16  + (size_t)i*NE*NM;
        const float* g_i  = lng + (size_t)i*NE;       const float* b_i  = lnb + (size_t)i*NE;
        const __half* w1_i = w116 + (size_t)i*NE*HID; const float* b1_i = b1 + (size_t)i*HID;
        const __half* w2_i = w216 + (size_t)i*HID*NE; const float* b2_i = b2 + (size_t)i*NE;

        // zero accumulators (sumsq + ordered-max cells)
        zero_k<<<ROWS/256,256>>>(nq, ROWS);
        zero_k<<<ROWS/256,256>>>(nk, ROWS);
        zerou_k<<<1,256>>>(mxo, 1);
        zerou_k<<<1,256>>>(mxqo, 1);

        // projections: Q/K with fused per-row sumsq, V plain
        hgemm<0,0,0,1,1>(h16, NE,0, wq_i, NE,0, nullptr, q16, NE,0, bq_i, ROWS, NE, NE, 1, nq);
        hgemm<0,0,0,1,1>(h16, NE,0, wk_i, NE,0, nullptr, k16, NE,0, bk_i, ROWS, NE, NE, 1, nk);
        hgemm<0,0,0,1,0>(h16, NE,0, wv_i, NE,0, nullptr, v16, NE,0, bv_i, ROWS, NE, NE, 1);

        // phi-q FULLY FUSED: logits + rowmax + exp -> pq16 (row-normalized)
        hgemm<0,0,0,0,5>(q16, NE,0, r_i, NM,0, nullptr, pq16, NM,0, nullptr, ROWS, NM, NE, 1, nq, rowq);
        maxredA_k<<<256,256>>>(rowq, ROWS, mxqo);

        // phi-k: fused logits + rowmax (logits fp32 in pk, rowmax in part)
        hgemm<0,0,1,0,2>(k16, NE,0, r_i, NM,0, pk, nullptr, NM,0, nullptr, ROWS, NM, NE, 1, nk, part);
        maxredA_k<<<256,256>>>(part, ROWS, mxo);
        maxredB_k<<<NB,1024>>>(part, bmk);
        phiexp_pk_k<<<pm_grid,256>>>(pk, pk16, bmk, nHM);

        // kv[b] = pk16[b]^T @ v16[b]  — split-K, fp32 atomic accumulation
        zero_k<<<((size_t)NB*NM*NE+255)/256,256>>>(kv32, (size_t)NB*NM*NE);
        hgemm_splitk_kv(pk16, v16, kv32);
        conv16(kv32, kv16, (size_t)NB*NM*NE);

        // z'[b] = sum_s pk16[b,s,:]
        zero_k<<<(NB*NM+255)/256,256>>>(z, NB*NM);
        colsum16_k<<<dim3(NB,32),128>>>(pk16, z);

        // inv[row] = G / (G*(pq16.z') + 1e-6)
        den_k<<<ROWS/8,256>>>(pq16, z, rowq, mxqo, bmk, mxo, inv);

        // num GEMM with fused row scaling -> q16
        hgemm<0,0,0,1,3>(pq16, NM, (size_t)NS*NM, kv16, NE, (size_t)NM*NE,
                         nullptr, q16, NE, (size_t)NS*NE, nullptr, NS, NE, NM, NB, inv);

        // a -> k (fp32, LN input)
        hgemm<0,0,1,0,0>(q16, NE,0, wo_i, NE,0, k, nullptr, NE,0, bo_i, ROWS, NE, NE, 1);

        // y -> v16 (LayerNorm)
        ln_k<<<ROWS,256>>>(k, v16, g_i, b_i);

        // ff1 = gelu(y @ W1 + b1) -> ff16
        hgemm<0,1,0,1,0>(v16, NE,0, w1_i, HID,0, nullptr, ff16, HID,0, b1_i, ROWS, HID, NE, 1);
        // ff2 with fused residual: h = ff2 + b2 + h ; dual-write h16
        hgemm<0,0,1,1,4>(ff16, HID,0, w2_i, NE,0, h, h16, NE,0, b2_i, ROWS, NE, HID, 1);
    }

    // head: pooled = h[:,0,:] — tiny, fp32 path
    {
        dim3 g1((256 + BN - 1) / BN, (NB + BM - 1) / BM);
        gemm_k<2><<<g1, 256>>>(h, NS*NE, Wr1, 256, r1, 256, br1, NB, 256, NE);
        dim3 g2(1, 1);
        gemm_k<0><<<g2, 256>>>(r1, 256, Wr2, 1, out, 1, br2, NB, 1, 256);
    }
}

// round 16
// speedup vs baseline: 1.0159x; 1.0048x over previous
#include <cuda_runtime.h>
#include <cuda_fp16.h>
#include <math.h>
#include <stdint.h>

#define NB 16
#define NS 4096
#define NDIN 64
#define NE 512
#define NM 128
#define NL 4
#define ROWS (NB*NS)        /* 65536 */
#define HID (4*NE)          /* 2048 */
#define KV_SPLIT 8

// ---------------- scratch (device globals; no allocations allowed) ----------
__device__ float g_h [(size_t)ROWS*NE];
__device__ float g_pk[(size_t)ROWS*NM];   // pk logits (fp32)
__device__ float g_kv32[(size_t)NB*NM*NE];
__device__ float g_z [NB*NM];
__device__ float g_part [ROWS];   // per-row max (pk pass)
__device__ float g_rowq [ROWS];   // per-row max for pq
__device__ float g_nq  [ROWS];    // per-row sum-of-squares (q)
__device__ float g_nk  [ROWS];    // per-row sum-of-squares (k)
__device__ float g_inv [ROWS];    // per-row 1/den factor
__device__ unsigned g_mxo [1];    // global max (pk), ordered-uint encoding
__device__ unsigned g_mxqo[1];    // global max (pq), ordered-uint encoding
__device__ float g_bmk [NB];      // per-batch max (pk)
__device__ float g_r1[16*256];

// fp16 mirrors
__device__ __half g_h16 [(size_t)ROWS*NE];
__device__ __half g_q16 [(size_t)ROWS*NE];
__device__ __half g_k16 [(size_t)ROWS*NE];
__device__ __half g_v16 [(size_t)ROWS*NE];
__device__ __half g_pq16[(size_t)ROWS*NM];
__device__ __half g_pk16[(size_t)ROWS*NM];
__device__ __half g_kv16[(size_t)NB*NM*NE];
__device__ __half g_ff16[(size_t)ROWS*HID];
__device__ __half g_x16 [(size_t)ROWS*NDIN];
__device__ __half g_wi16[NDIN*NE];
__device__ __half g_wq16[(size_t)NL*NE*NE];
__device__ __half g_wk16[(size_t)NL*NE*NE];
__device__ __half g_wv16[(size_t)NL*NE*NE];
__device__ __half g_wo16[(size_t)NL*NE*NE];
__device__ __half g_r16 [(size_t)NL*NE*NM];
__device__ __half g_w116[(size_t)NL*NE*HID];
__device__ __half g_w216[(size_t)NL*HID*NE];

// ================= helpers =================
__device__ __forceinline__ uint32_t smem_u32(const void* p) {
    uint32_t r;
    asm("{ .reg .u64 t; cvta.to.shared.u64 t, %1; cvt.u32.u64 %0, t; }" : "=r"(r) : "l"(p));
    return r;
}
__device__ __forceinline__ void cp_async16(uint32_t saddr, const void* g) {
    asm volatile("cp.async.cg.shared.global [%0], [%1], 16;" :: "r"(saddr), "l"(g));
}
__device__ __forceinline__ void ldsm_x4(uint32_t r[4], uint32_t addr) {
    asm volatile("ldmatrix.sync.aligned.m8n8.x4.shared.b16 {%0,%1,%2,%3}, [%4];"
                 : "=r"(r[0]), "=r"(r[1]), "=r"(r[2]), "=r"(r[3]) : "r"(addr));
}
__device__ __forceinline__ void ldsm_x4_t(uint32_t r[4], uint32_t addr) {
    asm volatile("ldmatrix.sync.aligned.m8n8.x4.trans.shared.b16 {%0,%1,%2,%3}, [%4];"
                 : "=r"(r[0]), "=r"(r[1]), "=r"(r[2]), "=r"(r[3]) : "r"(addr));
}
__device__ __forceinline__ void mma_f16(float c[4], const uint32_t a[4], const uint32_t b[2]) {
    asm volatile(
        "mma.sync.aligned.m16n8k16.row.col.f32.f16.f16.f32 "
        "{%0,%1,%2,%3}, {%4,%5,%6,%7}, {%8,%9}, {%0,%1,%2,%3};"
        : "+f"(c[0]), "+f"(c[1]), "+f"(c[2]), "+f"(c[3])
        : "r"(a[0]), "r"(a[1]), "r"(a[2]), "r"(a[3]), "r"(b[0]), "r"(b[1]));
}
// monotonic float<->uint encoding: a<=b (float) <=> ford(a)<=ford(b) (uint)
__device__ __forceinline__ unsigned ford(float f) {
    unsigned u = __float_as_uint(f);
    return (u & 0x80000000u) ? ~u : (u | 0x80000000u);
}
__device__ __forceinline__ float funord(unsigned u) {
    return __uint_as_float((u & 0x80000000u) ? (u & 0x7fffffffu) : ~u);
}

// ================= fp16 mma GEMM with fused epilogues =================
// 128 threads / 4 warps; CTA tile 128x128; warp tile 64x64; BK=32, 4 stages.
// MODE 0: plain; MODE 1: SUMSQ; MODE 2: PHI; MODE 3: SCALEROW; MODE 4: RESID;
// MODE 5: PHIEXP; MODE 6: SPLITK (blockIdx.y = k-chunk, atomicAdd fp32 into C).

#define BKH 32
#define A_HS 40
#define T_HS 136
#define HG_STAGES 4

template<int TRANS_A>
__device__ __forceinline__ void h_fill(const __half* __restrict__ A, int lda,
                                       const __half* __restrict__ B, int ldb,
                                       int m0, int n0, int kof,
                                       uint32_t sa, uint32_t sb, int tid) {
    if (!TRANS_A) {
#pragma unroll
        for (int i = 0; i < 4; i++) {
            int lin = (i << 7) + tid;
            int row = lin >> 2, c = lin & 3;
            cp_async16(sa + (uint32_t)(row * A_HS + (c << 3)) * 2,
                       A + (size_t)(m0 + row) * lda + kof + (c << 3));
        }
    } else {
#pragma unroll
        for (int i = 0; i < 4; i++) {
            int lin = (i << 7) + tid;
            int row = lin >> 4, c = lin & 15;
            cp_async16(sa + (uint32_t)(row * T_HS + (c << 3)) * 2,
                       A + (size_t)(kof + row) * lda + m0 + (c << 3));
        }
    }
#pragma unroll
    for (int i = 0; i < 4; i++) {
        int lin = (i << 7) + tid;
        int row = lin >> 4, c = lin & 15;
        cp_async16(sb + (uint32_t)(row * T_HS + (c << 3)) * 2,
                   B + (size_t)(kof + row) * ldb + n0 + (c << 3));
    }
}

template<int TRANS_A, int ACT, int WF32, int WF16, int MODE>
__global__ __launch_bounds__(128, 2)
void hgemm_k(const __half* __restrict__ A, int lda, size_t sAs,
             const __half* __restrict__ B, int ldb, size_t sBs,
             float* __restrict__ C, __half* __restrict__ C16, int ldc, size_t sCs,
             const float* __restrict__ bias, int K,
             float* __restrict__ aux1, float* __restrict__ aux2)
{
    constexpr int ATILE_B = TRANS_A ? (BKH * T_HS * 2) : (128 * A_HS * 2);
    constexpr int STAGE_B = ATILE_B + BKH * T_HS * 2;

    extern __shared__ __half hsm[];
    uint32_t smb = smem_u32(hsm);
    int tid = threadIdx.x;
    int wid = tid >> 5, lane = tid & 31;
    int group = lane >> 3, lr = lane & 7;
    int g = lane >> 2, t4 = lane & 3;

    A += (size_t)blockIdx.z * sAs;
    B += (size_t)blockIdx.z * sBs;
    int m0 = (MODE == 6) ? 0 : (blockIdx.y << 7);
    int kb = (MODE == 6) ? (blockIdx.y * K) : 0;   // k-chunk base for split-K
    int n0 = blockIdx.x << 7;
    int wm = wid & 1, wn = wid >> 1;

    float c[4][8][4];
#pragma unroll
    for (int a = 0; a < 4; a++)
#pragma unroll
        for (int b = 0; b < 8; b++)
#pragma unroll
            for (int r = 0; r < 4; r++) c[a][b][r] = 0.f;

    int nk = K >> 5;

#pragma unroll
    for (int s = 0; s < HG_STAGES - 1; s++) {
        if (s < nk) {
            uint32_t sa = smb + (uint32_t)s * STAGE_B;
            h_fill<TRANS_A>(A, lda, B, ldb, m0, n0, kb + (s << 5), sa, sa + ATILE_B, tid);
        }
        asm volatile("cp.async.commit_group;");
    }

    for (int kt = 0; kt < nk; kt++) {
        asm volatile("cp.async.wait_group %0;" :: "n"(HG_STAGES - 2));
        __syncthreads();

        int nxt = kt + HG_STAGES - 1;
        if (nxt < nk) {
            uint32_t sa = smb + (uint32_t)(nxt & (HG_STAGES - 1)) * STAGE_B;
            h_fill<TRANS_A>(A, lda, B, ldb, m0, n0, kb + (nxt << 5), sa, sa + ATILE_B, tid);
        }
        asm volatile("cp.async.commit_group;");

        uint32_t sa = smb + (uint32_t)(kt & (HG_STAGES - 1)) * STAGE_B;
        uint32_t sb = sa + ATILE_B;
#pragma unroll
        for (int ks = 0; ks < 2; ks++) {
            uint32_t af[4][4];
#pragma unroll
            for (int mi = 0; mi < 4; mi++) {
                uint32_t addr;
                if (!TRANS_A) {
                    int arow = (wm << 6) + (mi << 4) + ((group & 1) << 3) + lr;
                    int acol = (ks << 4) + ((group >> 1) << 3);
                    addr = sa + (uint32_t)(arow * A_HS + acol) * 2;
                    ldsm_x4(af[mi], addr);
                } else {
                    int krow = (ks << 4) + ((group >> 1) << 3) + lr;
                    int mcol = (wm << 6) + (mi << 4) + ((group & 1) << 3);
                    addr = sa + (uint32_t)(krow * T_HS + mcol) * 2;
                    ldsm_x4_t(af[mi], addr);
                }
            }
            uint32_t bf[4][4];
#pragma unroll
            for (int np = 0; np < 4; np++) {
                int krow = (ks << 4) + ((group & 1) << 3) + lr;
                int ncol = (wn << 6) + (np << 4) + ((group >> 1) << 3);
                ldsm_x4_t(bf[np], sb + (uint32_t)(krow * T_HS + ncol) * 2);
            }
#pragma unroll
            for (int mi = 0; mi < 4; mi++)
#pragma unroll
                for (int ni = 0; ni < 8; ni++)
                    mma_f16(c[mi][ni], af[mi], &bf[ni >> 1][(ni & 1) << 1]);
        }
    }

    // ---- epilogue ----
    if (MODE == 2 || MODE == 5) __syncthreads();     // smem reused as logit stage
    float* stage = (float*)hsm;
    int auxrows = (int)(sCs / (size_t)ldc);
    const float GK = 0.7071067811865476f;
    const float PSCALE = 0.21022410381342865f;   // 512^-0.25
    const float PS2    = 0.02209708691207961f;   // 0.5 * 512^-0.5
#pragma unroll
    for (int mi = 0; mi < 4; mi++) {
        int r = (wm << 6) + (mi << 4) + g;
        size_t rowoff0 = (size_t)blockIdx.z * sCs + (size_t)(m0 + r) * ldc;
        size_t rowoff1 = rowoff0 + (size_t)8 * ldc;
        int ar0 = blockIdx.z * auxrows + m0 + r;
        int ar1 = ar0 + 8;
        float n2a = 0.f, n2b = 0.f, iv0 = 0.f, iv1 = 0.f;
        if (MODE == 2 || MODE == 5) { n2a = aux1[ar0]; n2b = aux1[ar1]; }
        if (MODE == 3) { iv0 = aux1[ar0]; iv1 = aux1[ar1]; }
        float ssq0 = 0.f, ssq1 = 0.f;
#pragma unroll
        for (int ni = 0; ni < 8; ni++) {
            int nn = n0 + (wn << 6) + (ni << 3) + (t4 << 1);
            float v0 = c[mi][ni][0], v1 = c[mi][ni][1];
            float v2 = c[mi][ni][2], v3 = c[mi][ni][3];
            if (bias) {
                float b0 = __ldg(bias + nn), b1 = __ldg(bias + nn + 1);
                v0 += b0; v1 += b1; v2 += b0; v3 += b1;
            }
            if (ACT == 1) {
                v0 = 0.5f * v0 * (1.f + erff(v0 * GK));
                v1 = 0.5f * v1 * (1.f + erff(v1 * GK));
                v2 = 0.5f * v2 * (1.f + erff(v2 * GK));
                v3 = 0.5f * v3 * (1.f + erff(v3 * GK));
            }
            if (MODE == 1) {
                ssq0 += v0 * v0 + v1 * v1;
                ssq1 += v2 * v2 + v3 * v3;
            }
            if (MODE == 2 || MODE == 5) {
                int rl = (wm << 6) + (mi << 4) + g;
                v0 = fmaf(v0, PSCALE, -PS2 * n2a);
                v1 = fmaf(v1, PSCALE, -PS2 * n2a);
                v2 = fmaf(v2, PSCALE, -PS2 * n2b);
                v3 = fmaf(v3, PSCALE, -PS2 * n2b);
                int nl = (wn << 6) + (ni << 3) + (t4 << 1);
                stage[rl * 132 + nl] = v0;       stage[rl * 132 + nl + 1] = v1;
                stage[(rl + 8) * 132 + nl] = v2; stage[(rl + 8) * 132 + nl + 1] = v3;
            }
            if (MODE == 3) { v0 *= iv0; v1 *= iv0; v2 *= iv1; v3 *= iv1; }
            if (MODE == 4) {
                float2 r0 = *(float2*)(C + rowoff0 + nn);
                float2 r1 = *(float2*)(C + rowoff1 + nn);
                v0 += r0.x; v1 += r0.y; v2 += r1.x; v3 += r1.y;
            }
            if (MODE == 6) {
                atomicAdd(C + rowoff0 + nn, v0);
                atomicAdd(C + rowoff0 + nn + 1, v1);
                atomicAdd(C + rowoff1 + nn, v2);
                atomicAdd(C + rowoff1 + nn + 1, v3);
            }
            if (WF32) {
                *(float2*)(C + rowoff0 + nn) = make_float2(v0, v1);
                *(float2*)(C + rowoff1 + nn) = make_float2(v2, v3);
            }
            if (WF16) {
                *(__half2*)(C16 + rowoff0 + nn) = __floats2half2_rn(v0, v1);
                *(__half2*)(C16 + rowoff1 + nn) = __floats2half2_rn(v2, v3);
            }
        }
        if (MODE == 1) {
            ssq0 += __shfl_xor_sync(0xffffffffu, ssq0, 1);
            ssq0 += __shfl_xor_sync(0xffffffffu, ssq0, 2);
            ssq1 += __shfl_xor_sync(0xffffffffu, ssq1, 1);
            ssq1 += __shfl_xor_sync(0xffffffffu, ssq1, 2);
            if (t4 == 0) {
                atomicAdd(&aux1[ar0], ssq0);
                atomicAdd(&aux1[ar1], ssq1);
            }
        }
    }
    if (MODE == 2 || MODE == 5) {
        __syncthreads();
        int rr = tid;                        // one thread per row (128)
        const float* rp = stage + rr * 132;
        float m = -INFINITY;
#pragma unroll
        for (int j = 0; j < 128; j++) m = fmaxf(m, rp[j]);
        aux2[m0 + rr] = m;
        if (MODE == 5) {
            __half* dst = C16 + (size_t)(m0 + rr) * ldc;
#pragma unroll
            for (int j = 0; j < 128; j += 2) {
                float e0 = expf(rp[j]     - m) * 0.08838834764831845f;
                float e1 = expf(rp[j + 1] - m) * 0.08838834764831845f;
                *(__half2*)(dst + j) = __floats2half2_rn(e0, e1);
            }
        }
    }
}

// ================= fp32 fallback SGEMM (head only) =================
#define BM 128
#define BN 128
#define BK 8

template<int ACT>
__global__ __launch_bounds__(256)
void gemm_k(const float* __restrict__ A, int lda,
            const float* __restrict__ Bm, int ldb,
            float* __restrict__ C, int ldc,
            const float* __restrict__ bias,
            int M, int N, int K)
{
    int m0 = blockIdx.y * BM;
    int n0 = blockIdx.x * BN;

    __shared__ float As[BK][BM];
    __shared__ float Bs[BK][BN];

    int tid = threadIdx.x;
    int tx = tid & 15, ty = tid >> 4;

    float acc[8][8];
#pragma unroll
    for (int i = 0; i < 8; i++)
#pragma unroll
        for (int j = 0; j < 8; j++) acc[i][j] = 0.f;

    float ar[8], br[8];

    for (int k0 = 0; k0 < K; k0 += BK) {
        {
            int m  = tid >> 1;
            int kk = (tid & 1) * 4;
            bool mok = (m0 + m) < M;
            const float* src = A + (size_t)(m0 + m) * lda + k0 + kk;
#pragma unroll
            for (int i = 0; i < 4; i++)
                As[kk + i][m] = mok ? src[i] : 0.f;
        }
        {
            int k = tid >> 5;
            int n = (tid & 31) * 4;
            const float* src = Bm + (size_t)(k0 + k) * ldb + n0 + n;
#pragma unroll
            for (int i = 0; i < 4; i++) {
                float vv = 0.f;
                if (n0 + n + i < N) vv = src[i];
                Bs[k][n + i] = vv;
            }
        }
        __syncthreads();
#pragma unroll
        for (int k = 0; k < BK; k++) {
            *(float4*)&ar[0] = *(float4*)&As[k][ty * 4];
            *(float4*)&ar[4] = *(float4*)&As[k][64 + ty * 4];
            *(float4*)&br[0] = *(float4*)&Bs[k][tx * 4];
            *(float4*)&br[4] = *(float4*)&Bs[k][64 + tx * 4];
#pragma unroll
            for (int i = 0; i < 8; i++)
#pragma unroll
                for (int j = 0; j < 8; j++)
                    acc[i][j] = fmaf(ar[i], br[j], acc[i][j]);
        }
        __syncthreads();
    }

#pragma unroll
    for (int i = 0; i < 8; i++) {
        int m = m0 + ((i < 4) ? (ty * 4 + i) : (64 + ty * 4 + i - 4));
        if (m >= M) continue;
#pragma unroll
        for (int j = 0; j < 8; j++) {
            int n = n0 + ((j < 4) ? (tx * 4 + j) : (64 + tx * 4 + j - 4));
            if (n >= N) continue;
            float vv = acc[i][j];
            if (bias) vv += bias[n];
            if (ACT == 2) vv = fmaxf(vv, 0.f);
            C[(size_t)m * ldc + n] = vv;
        }
    }
}

// ---------------- elementwise / reduction kernels ---------------------------

__global__ void conv16_k(const float* __restrict__ in, __half* __restrict__ out, size_t n) {
    size_t i = ((size_t)blockIdx.x * 256 + threadIdx.x) * 4;
    if (i < n) {
        float4 v = *(const float4*)(in + i);
        *(__half2*)(out + i)     = __floats2half2_rn(v.x, v.y);
        *(__half2*)(out + i + 2) = __floats2half2_rn(v.z, v.w);
    }
}

__global__ void addpos_k(float* __restrict__ h, __half* __restrict__ h16,
                         const float* __restrict__ pos) {
    size_t i = (size_t)blockIdx.x * 256 + threadIdx.x;
    if (i < (size_t)ROWS * NE) {
        float v = h[i] + pos[i % ((size_t)NS * NE)];
        h[i] = v;
        h16[i] = __float2half_rn(v);
    }
}

__global__ void zero_k(float* p, size_t n) {
    size_t i = (size_t)blockIdx.x * 256 + threadIdx.x;
    if (i < n) p[i] = 0.f;
}

// zero two float arrays + two ordered-max cells in one launch
__global__ void zero2_k(float* a, float* b, size_t n, unsigned* u0, unsigned* u1) {
    size_t i = (size_t)blockIdx.x * 256 + threadIdx.x;
    if (i < n) { a[i] = 0.f; b[i] = 0.f; }
    if (i == 0) { u0[0] = 0u; u1[0] = 0u; }   // 0 precedes ford(-inf)
}

// grid-wide max of part[0..n) into ordered-uint cell
__global__ void maxredA_k(const float* __restrict__ part, int n, unsigned* __restrict__ out) {
    __shared__ float sh[256];
    int t = threadIdx.x;
    float m = -INFINITY;
    for (int i = blockIdx.x * 256 + t; i < n; i += gridDim.x * 256)
        m = fmaxf(m, part[i]);
    sh[t] = m; __syncthreads();
    for (int o = 128; o > 0; o >>= 1) { if (t < o) sh[t] = fmaxf(sh[t], sh[t + o]); __syncthreads(); }
    if (t == 0) atomicMax(out, ford(sh[0]));
}

// per-batch max -> bmk[b], AND global max -> atomicMax(mxo)
__global__ void maxredBA_k(const float* __restrict__ part, float* __restrict__ bmk,
                           unsigned* __restrict__ mxo) {
    __shared__ float sh[1024];
    int t = threadIdx.x, b = blockIdx.x;
    const float* p = part + (size_t)b * NS;
    float m = -INFINITY;
    for (int i = t; i < NS; i += 1024) m = fmaxf(m, p[i]);
    sh[t] = m; __syncthreads();
    for (int o = 512; o > 0; o >>= 1) { if (t < o) sh[t] = fmaxf(sh[t], sh[t + o]); __syncthreads(); }
    if (t == 0) {
        bmk[b] = sh[0];
        atomicMax(mxo, ford(sh[0]));
    }
}

// pk: read fp32 logits, write fp16 exp(l - batchmax)/sqrt(M)
__global__ void phiexp_pk_k(const float* __restrict__ G, __half* __restrict__ G16,
                            const float* __restrict__ bmax, size_t n) {
    size_t i = (size_t)blockIdx.x * 256 + threadIdx.x;
    if (i < n) {
        float bm = bmax[i >> 19];
        G16[i] = __float2half_rn(expf(G[i] - bm) * 0.08838834764831845f);
    }
}

// z'[b,m] = sum_s pk16[b,s,m]
__global__ void colsum16_k(const __half* __restrict__ pk16, float* __restrict__ z) {
    int b = blockIdx.x, chunk = blockIdx.y, m = threadIdx.x;
    const __half* p = pk16 + (size_t)b * NS * NM + (size_t)chunk * 128 * NM + m;
    float s = 0.f;
    for (int i = 0; i < 128; i++) s += __half2float(p[(size_t)i * NM]);
    atomicAdd(&z[b * NM + m], s);
}

// inv[row] = G / (G*s + 1e-6),  G = exp(rowq-mxq + bmk-mx),  s = pq16 . z'
__global__ void den_k(const __half* __restrict__ pq16, const float* __restrict__ z,
                      const float* __restrict__ rowq, const unsigned* __restrict__ mxqo,
                      const float* __restrict__ bmk, const unsigned* __restrict__ mxko,
                      float* __restrict__ inv) {
    int warp = threadIdx.x >> 5, lane = threadIdx.x & 31;
    int row = blockIdx.x * 8 + warp;
    int b = row / NS;
    const __half* p = pq16 + (size_t)row * NM;
    const float* zz = z + b * NM;
    float s = 0.f;
#pragma unroll
    for (int j = 0; j < 4; j++)
        s = fmaf(__half2float(p[lane + 32 * j]), zz[lane + 32 * j], s);
#pragma unroll
    for (int o = 16; o > 0; o >>= 1) s += __shfl_xor_sync(0xffffffffu, s, o);
    if (lane == 0) {
        float mxq = funord(mxqo[0]);
        float mxk = funord(mxko[0]);
        float G = expf((rowq[row] - mxq) + (bmk[b] - mxk));
        inv[row] = G / (fmaf(G, s, 1e-6f));
    }
}

// LayerNorm over E=512; fp16 in, fp16 out
__global__ void ln16_k(const __half* __restrict__ in, __half* __restrict__ out16,
                       const float* __restrict__ g, const float* __restrict__ b) {
    int row = blockIdx.x, t = threadIdx.x;
    __shared__ float sh[256];
    const __half* a = in + (size_t)row * NE;
    float x0 = __half2float(a[t]), x1 = __half2float(a[t + 256]);
    sh[t] = x0 + x1; __syncthreads();
    for (int o = 128; o > 0; o >>= 1) { if (t < o) sh[t] += sh[t + o]; __syncthreads(); }
    float mu = sh[0] * (1.f / NE);
    __syncthreads();
    float d0 = x0 - mu, d1 = x1 - mu;
    sh[t] = d0 * d0 + d1 * d1; __syncthreads();
    for (int o = 128; o > 0; o >>= 1) { if (t < o) sh[t] += sh[t + o]; __syncthreads(); }
    float rstd = rsqrtf(sh[0] * (1.f / NE) + 1e-5f);
    out16[(size_t)row * NE + t]       = __float2half_rn(d0 * rstd * g[t] + b[t]);
    out16[(size_t)row * NE + t + 256] = __float2half_rn(d1 * rstd * g[t + 256] + b[t + 256]);
}

// ---------------- host-side dispatch ----------------------------------------

template<int TRANS_A, int ACT, int WF32, int WF16, int MODE>
static void hgemm(const __half* A, int lda, size_t sA,
                  const __half* Bm, int ldb, size_t sB,
                  float* C, __half* C16, int ldc, size_t sC,
                  const float* bias, int M, int N, int K, int batch,
                  float* aux1 = nullptr, float* aux2 = nullptr)
{
    constexpr int ATILE_B = TRANS_A ? (BKH * T_HS * 2) : (128 * A_HS * 2);
    constexpr int SMEM = HG_STAGES * (ATILE_B + BKH * T_HS * 2);
    cudaFuncSetAttribute(hgemm_k<TRANS_A, ACT, WF32, WF16, MODE>,
                         cudaFuncAttributeMaxDynamicSharedMemorySize, SMEM);
    dim3 grid(N >> 7, M >> 7, batch);
    hgemm_k<TRANS_A, ACT, WF32, WF16, MODE><<<grid, 128, SMEM>>>(
        A, lda, sA, Bm, ldb, sB, C, C16, ldc, sC, bias, K, aux1, aux2);
}

// split-K variant: grid.y = k-chunks, M must be 128
static void hgemm_splitk_kv(const __half* A, const __half* Bm, float* C32)
{
    constexpr int ATILE_B = BKH * T_HS * 2;
    constexpr int SMEM = HG_STAGES * (ATILE_B + BKH * T_HS * 2);
    cudaFuncSetAttribute(hgemm_k<1, 0, 0, 0, 6>,
                         cudaFuncAttributeMaxDynamicSharedMemorySize, SMEM);
    dim3 grid(NE >> 7, KV_SPLIT, NB);
    hgemm_k<1, 0, 0, 0, 6><<<grid, 128, SMEM>>>(
        A, NM, (size_t)NS * NM, Bm, NE, (size_t)NS * NE,
        C32, nullptr, NE, (size_t)NM * NE, nullptr, NS / KV_SPLIT, nullptr, nullptr);
}

static void conv16(const float* in, __half* out, size_t n) {
    conv16_k<<<(unsigned)((n / 4 + 255) / 256), 256>>>(in, out, n);
}

extern "C" void kernel_launch(void* const* d_in, const int* in_sizes, int n_in,
                              void* d_out, int out_size)
{
    const float* x    = (const float*)d_in[0];
    const float* Wi   = (const float*)d_in[1];
    const float* bi   = (const float*)d_in[2];
    const float* pos  = (const float*)d_in[3];
    const float* Wq   = (const float*)d_in[4];
    const float* bq   = (const float*)d_in[5];
    const float* Wk   = (const float*)d_in[6];
    const float* bk   = (const float*)d_in[7];
    const float* Wv   = (const float*)d_in[8];
    const float* bv   = (const float*)d_in[9];
    const float* Wo   = (const float*)d_in[10];
    const float* bo   = (const float*)d_in[11];
    const float* R    = (const float*)d_in[12];
    const float* lng  = (const float*)d_in[13];
    const float* lnb  = (const float*)d_in[14];
    const float* W1   = (const float*)d_in[15];
    const float* b1   = (const float*)d_in[16];
    const float* W2   = (const float*)d_in[17];
    const float* b2   = (const float*)d_in[18];
    const float* Wr1  = (const float*)d_in[19];
    const float* br1  = (const float*)d_in[20];
    const float* Wr2  = (const float*)d_in[21];
    const float* br2  = (const float*)d_in[22];
    float* out = (float*)d_out;

    float *h,*pk,*kv32,*z,*part,*rowq,*nq,*nk,*inv,*bmk,*r1;
    unsigned *mxo,*mxqo;
    __half *h16,*q16,*k16,*v16,*pq16,*pk16,*kv16,*ff16,*x16;
    __half *wi16,*wq16,*wk16,*wv16,*wo16,*r16,*w116,*w216;
    cudaGetSymbolAddress((void**)&h,  g_h);
    cudaGetSymbolAddress((void**)&pk, g_pk);
    cudaGetSymbolAddress((void**)&kv32, g_kv32);
    cudaGetSymbolAddress((void**)&z,  g_z);
    cudaGetSymbolAddress((void**)&part, g_part);
    cudaGetSymbolAddress((void**)&rowq, g_rowq);
    cudaGetSymbolAddress((void**)&nq, g_nq);
    cudaGetSymbolAddress((void**)&nk, g_nk);
    cudaGetSymbolAddress((void**)&inv, g_inv);
    cudaGetSymbolAddress((void**)&mxo, g_mxo);
    cudaGetSymbolAddress((void**)&mxqo, g_mxqo);
    cudaGetSymbolAddress((void**)&bmk, g_bmk);
    cudaGetSymbolAddress((void**)&r1, g_r1);
    cudaGetSymbolAddress((void**)&h16,  g_h16);
    cudaGetSymbolAddress((void**)&q16,  g_q16);
    cudaGetSymbolAddress((void**)&k16,  g_k16);
    cudaGetSymbolAddress((void**)&v16,  g_v16);
    cudaGetSymbolAddress((void**)&pq16, g_pq16);
    cudaGetSymbolAddress((void**)&pk16, g_pk16);
    cudaGetSymbolAddress((void**)&kv16, g_kv16);
    cudaGetSymbolAddress((void**)&ff16, g_ff16);
    cudaGetSymbolAddress((void**)&x16,  g_x16);
    cudaGetSymbolAddress((void**)&wi16, g_wi16);
    cudaGetSymbolAddress((void**)&wq16, g_wq16);
    cudaGetSymbolAddress((void**)&wk16, g_wk16);
    cudaGetSymbolAddress((void**)&wv16, g_wv16);
    cudaGetSymbolAddress((void**)&wo16, g_wo16);
    cudaGetSymbolAddress((void**)&r16,  g_r16);
    cudaGetSymbolAddress((void**)&w116, g_w116);
    cudaGetSymbolAddress((void**)&w216, g_w216);

    const size_t nHE = (size_t)ROWS * NE;
    const size_t nHM = (size_t)ROWS * NM;
    int ew_grid = (int)((nHE + 255) / 256);
    int pm_grid = (int)((nHM + 255) / 256);

    // ---- fp16 weight/input mirrors ----
    conv16(x,  x16, (size_t)ROWS * NDIN);
    conv16(Wi, wi16, (size_t)NDIN * NE);
    conv16(Wq, wq16, (size_t)NL * NE * NE);
    conv16(Wk, wk16, (size_t)NL * NE * NE);
    conv16(Wv, wv16, (size_t)NL * NE * NE);
    conv16(Wo, wo16, (size_t)NL * NE * NE);
    conv16(R,  r16,  (size_t)NL * NE * NM);
    conv16(W1, w116, (size_t)NL * NE * HID);
    conv16(W2, w216, (size_t)NL * HID * NE);

    // h = x @ Wi + bi ; then += pos (dual-write h16)
    hgemm<0,0,1,0,0>(x16, NDIN,0, wi16, NE,0, h, nullptr, NE,0, bi, ROWS, NE, NDIN, 1);
    addpos_k<<<ew_grid,256>>>(h, h16, pos);

    for (int i = 0; i < NL; i++) {
        const __half* wq_i = wq16 + (size_t)i*NE*NE;  const float* bq_i = bq + (size_t)i*NE;
        const __half* wk_i = wk16 + (size_t)i*NE*NE;  const float* bk_i = bk + (size_t)i*NE;
        const __half* wv_i = wv16 + (size_t)i*NE*NE;  const float* bv_i = bv + (size_t)i*NE;
        const __half* wo_i = wo16 + (size_t)i*NE*NE;  const float* bo_i = bo + (size_t)i*NE;
        const __half* r_i  = r16  + (size_t)i*NE*NM;
        const float* g_i  = lng + (size_t)i*NE;       const float* b_i  = lnb + (size_t)i*NE;
        const __half* w1_i = w116 + (size_t)i*NE*HID; const float* b1_i = b1 + (size_t)i*HID;
        const __half* w2_i = w216 + (size_t)i*HID*NE; const float* b2_i = b2 + (size_t)i*NE;

        // zero accumulators (sumsq x2 + both ordered-max cells, one launch)
        zero2_k<<<ROWS/256,256>>>(nq, nk, ROWS, mxo, mxqo);

        // projections: Q/K with fused per-row sumsq, V plain
        hgemm<0,0,0,1,1>(h16, NE,0, wq_i, NE,0, nullptr, q16, NE,0, bq_i, ROWS, NE, NE, 1, nq);
        hgemm<0,0,0,1,1>(h16, NE,0, wk_i, NE,0, nullptr, k16, NE,0, bk_i, ROWS, NE, NE, 1, nk);
        hgemm<0,0,0,1,0>(h16, NE,0, wv_i, NE,0, nullptr, v16, NE,0, bv_i, ROWS, NE, NE, 1);

        // phi-q FULLY FUSED: logits + rowmax + exp -> pq16 (row-normalized)
        hgemm<0,0,0,0,5>(q16, NE,0, r_i, NM,0, nullptr, pq16, NM,0, nullptr, ROWS, NM, NE, 1, nq, rowq);
        maxredA_k<<<256,256>>>(rowq, ROWS, mxqo);

        // phi-k: fused logits + rowmax (logits fp32 in pk, rowmax in part)
        hgemm<0,0,1,0,2>(k16, NE,0, r_i, NM,0, pk, nullptr, NM,0, nullptr, ROWS, NM, NE, 1, nk, part);
        maxredBA_k<<<NB,1024>>>(part, bmk, mxo);   // batch max + global max in one pass
        phiexp_pk_k<<<pm_grid,256>>>(pk, pk16, bmk, nHM);

        // kv[b] = pk16[b]^T @ v16[b]  — split-K, fp32 atomic accumulation
        zero_k<<<((size_t)NB*NM*NE+255)/256,256>>>(kv32, (size_t)NB*NM*NE);
        hgemm_splitk_kv(pk16, v16, kv32);
        conv16(kv32, kv16, (size_t)NB*NM*NE);

        // z'[b] = sum_s pk16[b,s,:]
        zero_k<<<(NB*NM+255)/256,256>>>(z, NB*NM);
        colsum16_k<<<dim3(NB,32),128>>>(pk16, z);

        // inv[row] = G / (G*(pq16.z') + 1e-6)
        den_k<<<ROWS/8,256>>>(pq16, z, rowq, mxqo, bmk, mxo, inv);

        // num GEMM with fused row scaling -> q16
        hgemm<0,0,0,1,3>(pq16, NM, (size_t)NS*NM, kv16, NE, (size_t)NM*NE,
                         nullptr, q16, NE, (size_t)NS*NE, nullptr, NS, NE, NM, NB, inv);

        // a -> k16 (fp16 only; LN reads fp16)
        hgemm<0,0,0,1,0>(q16, NE,0, wo_i, NE,0, nullptr, k16, NE,0, bo_i, ROWS, NE, NE, 1);

        // y -> v16 (LayerNorm, fp16 in/out)
        ln16_k<<<ROWS,256>>>(k16, v16, g_i, b_i);

        // ff1 = gelu(y @ W1 + b1) -> ff16
        hgemm<0,1,0,1,0>(v16, NE,0, w1_i, HID,0, nullptr, ff16, HID,0, b1_i, ROWS, HID, NE, 1);
        // ff2 with fused residual: h = ff2 + b2 + h ; dual-write h16
        hgemm<0,0,1,1,4>(ff16, HID,0, w2_i, NE,0, h, h16, NE,0, b2_i, ROWS, NE, HID, 1);
    }

    // head: pooled = h[:,0,:] — tiny, fp32 path
    {
        dim3 g1((256 + BN - 1) / BN, (NB + BM - 1) / BM);
        gemm_k<2><<<g1, 256>>>(h, NS*NE, Wr1, 256, r1, 256, br1, NB, 256, NE);
        dim3 g2(1, 1);
        gemm_k<0><<<g2, 256>>>(r1, 256, Wr2, 1, out, 1, br2, NB, 1, 256);
    }
}